// round 13
// baseline (speedup 1.0000x reference)
#include <cuda_runtime.h>
#include <cuda_fp16.h>
#include <cstdint>

#define BSZ 1024
#define S 62
#define DIM 65
#define H 10
#define NT 1024

#define W_FNH 0
#define W_FNL 2304
#define W_FRH 4608
#define W_FRL 6912
#define W_TNH 9216
#define W_TNL 11808
#define W_TRH 14400
#define W_TRL 16992
#define W_WH  19584
#define W_WL  24768
#define W_QH  29952
#define W_QL  32256
#define W_KH  34560
#define W_KL  36864
#define W_A1H 39168
#define W_A1L 41472
#define W_A2H 43776
#define W_A2L 46080
#define W_SS  48384
#define W_BIA 52992
#define W_G   55872
#define W_WRP 56016
#define W_FLG 56336
#define SMEM_WORDS 56340

__device__ uint32_t g_wh[40 * 72 * 36];
__device__ uint32_t g_wl[40 * 72 * 36];
__device__ float    g_gate[BSZ * DIM];
__device__ float    g_norms[BSZ * H];
__device__ int      g_ctr;

__device__ __forceinline__ void cp16(uint32_t dst, const void* src) {
    asm volatile("cp.async.cg.shared.global [%0], [%1], 16;\n" :: "r"(dst), "l"(src));
}
__device__ __forceinline__ void cp_commit() { asm volatile("cp.async.commit_group;\n"); }
__device__ __forceinline__ void cp_wait0()  { asm volatile("cp.async.wait_group 0;\n"); }

__device__ __forceinline__ void pack_hl(float x, float y, uint32_t& hw, uint32_t& lw) {
    const __half hx = __float2half_rn(x), hy = __float2half_rn(y);
    __half2 h = __halves2half2(hx, hy);
    __half2 l = __halves2half2(__float2half_rn(x - __half2float(hx)),
                               __float2half_rn(y - __half2float(hy)));
    hw = *reinterpret_cast<uint32_t*>(&h);
    lw = *reinterpret_cast<uint32_t*>(&l);
}
__device__ __forceinline__ void mma16(float* c, uint32_t a0, uint32_t a1,
                                      uint32_t a2, uint32_t a3, uint32_t b0, uint32_t b1) {
    asm volatile("mma.sync.aligned.m16n8k16.row.col.f32.f16.f16.f32 "
                 "{%0,%1,%2,%3}, {%4,%5,%6,%7}, {%8,%9}, {%0,%1,%2,%3};\n"
                 : "+f"(c[0]), "+f"(c[1]), "+f"(c[2]), "+f"(c[3])
                 : "r"(a0), "r"(a1), "r"(a2), "r"(a3), "r"(b0), "r"(b1));
}
__device__ __forceinline__ void mma8h(float* c, uint32_t a0, uint32_t a1, uint32_t b0) {
    asm volatile("mma.sync.aligned.m16n8k8.row.col.f32.f16.f16.f32 "
                 "{%0,%1,%2,%3}, {%4,%5}, {%6}, {%0,%1,%2,%3};\n"
                 : "+f"(c[0]), "+f"(c[1]), "+f"(c[2]), "+f"(c[3])
                 : "r"(a0), "r"(a1), "r"(b0));
}
__device__ __forceinline__ void ldsm4(uint32_t& r0, uint32_t& r1, uint32_t& r2,
                                      uint32_t& r3, uint32_t a) {
    asm volatile("ldmatrix.sync.aligned.m8n8.x4.shared.b16 {%0,%1,%2,%3}, [%4];\n"
                 : "=r"(r0), "=r"(r1), "=r"(r2), "=r"(r3) : "r"(a));
}
__device__ __forceinline__ void ldsm2(uint32_t& r0, uint32_t& r1, uint32_t a) {
    asm volatile("ldmatrix.sync.aligned.m8n8.x2.shared.b16 {%0,%1}, [%2];\n"
                 : "=r"(r0), "=r"(r1) : "r"(a));
}
__device__ __forceinline__ uint32_t s2u(const void* p) {
    return (uint32_t)__cvta_generic_to_shared(p);
}

__global__ void prep_kernel(const float* __restrict__ Fn, const float* __restrict__ Fr,
                            const float* __restrict__ Wg, const float* __restrict__ bg,
                            const float* __restrict__ Wq1, const float* __restrict__ Wk1,
                            const float* __restrict__ Wq2, const float* __restrict__ Wk2) {
    const int t = threadIdx.x;
    if (blockIdx.x < BSZ) {
        __shared__ float mean[132];
        const int b = blockIdx.x;
        if (t < 2 * DIM) {
            const float* src = (t < DIM) ? (Fn + (size_t)b * S * DIM + t)
                                         : (Fr + (size_t)b * S * DIM + t - DIM);
            float s = 0.f;
            for (int i = 0; i < S; i++) s += src[i * DIM];
            mean[t] = s * (1.0f / (float)S);
        }
        __syncthreads();
        if (t < DIM) {
            float acc = bg[t];
            const float* wr = Wg + t * 2 * DIM;
#pragma unroll 10
            for (int c = 0; c < 2 * DIM; c++) acc = fmaf(wr[c], mean[c], acc);
            g_gate[b * DIM + t] = 1.0f / (1.0f + __expf(-acc));
        }
    } else {
        const float* srcs[4] = { Wq1, Wk1, Wq2, Wk2 };
        const int total = 40 * 72 * 36;
        for (int idx = (blockIdx.x - BSZ) * 256 + t; idx < total; idx += 160 * 256) {
            const int m = idx / (72 * 36);
            const int rem = idx - m * 72 * 36;
            const int n = rem / 36, kw = rem - n * 36;
            const float* src = srcs[m & 3] + (m >> 2) * DIM * DIM;
            const int k0 = 2 * kw, k1 = k0 + 1;
            const float v0 = (n < DIM && k0 < DIM) ? src[n * DIM + k0] : 0.f;
            const float v1 = (n < DIM && k1 < DIM) ? src[n * DIM + k1] : 0.f;
            uint32_t hw, lw;
            pack_hl(v0, v1, hw, lw);
            g_wh[idx] = hw; g_wl[idx] = lw;
        }
    }
}

template <int EPI, int NS, bool K8>
__device__ __forceinline__ float mma_tile(
    const uint32_t* __restrict__ AH, const uint32_t* __restrict__ AL,
    const uint32_t* __restrict__ BH, const uint32_t* __restrict__ BL,
    const int mt, const int n0, void* c0, void* c1,
    const float* __restrict__ aux, const float scale)
{
    const int lane = threadIdx.x & 31, lr = lane >> 2, lc = lane & 3;
    float acc[NS][4];
#pragma unroll
    for (int ns = 0; ns < NS; ns++)
        acc[ns][0] = acc[ns][1] = acc[ns][2] = acc[ns][3] = 0.f;

    const int ar = lane & 15, ac4 = (lane >> 4) << 2;
    const uint32_t aH = s2u(AH) + (((mt * 16 + ar) * 36 + ac4) << 2);
    const uint32_t aL = s2u(AL) + (((mt * 16 + ar) * 36 + ac4) << 2);
    const int br = (lane & 7) | ((lane >> 4) << 3), bc4 = ((lane >> 3) & 1) << 2;
    const uint32_t bHp = s2u(BH) + (((n0 + br) * 36 + bc4) << 2);
    const uint32_t bLp = s2u(BL) + (((n0 + br) * 36 + bc4) << 2);
    const int xr = n0 + (NS & ~1) * 8 + (lane & 7), xc4 = ((lane >> 3) & 1) << 2;
    const uint32_t bHx = s2u(BH) + ((xr * 36 + xc4) << 2);
    const uint32_t bLx = s2u(BL) + ((xr * 36 + xc4) << 2);

#pragma unroll
    for (int s = 0; s < 4; s++) {
        const uint32_t kb = 32u * s;
        uint32_t a0, a1, a2, a3, e0, e1, e2, e3;
        ldsm4(a0, a1, a2, a3, aH + kb);
        ldsm4(e0, e1, e2, e3, aL + kb);
#pragma unroll
        for (int p = 0; p < NS / 2; p++) {
            uint32_t b0, b1, b2, b3, f0, f1, f2, f3;
            ldsm4(b0, b1, b2, b3, bHp + 2304u * p + kb);
            ldsm4(f0, f1, f2, f3, bLp + 2304u * p + kb);
            mma16(acc[2 * p], a0, a1, a2, a3, b0, b1);
            mma16(acc[2 * p], e0, e1, e2, e3, b0, b1);
            mma16(acc[2 * p], a0, a1, a2, a3, f0, f1);
            mma16(acc[2 * p + 1], a0, a1, a2, a3, b2, b3);
            mma16(acc[2 * p + 1], e0, e1, e2, e3, b2, b3);
            mma16(acc[2 * p + 1], a0, a1, a2, a3, f2, f3);
        }
        if (NS & 1) {
            uint32_t x0, x1, y0, y1;
            ldsm2(x0, x1, bHx + kb);
            ldsm2(y0, y1, bLx + kb);
            mma16(acc[NS - 1], a0, a1, a2, a3, x0, x1);
            mma16(acc[NS - 1], e0, e1, e2, e3, x0, x1);
            mma16(acc[NS - 1], a0, a1, a2, a3, y0, y1);
        }
    }
    if (K8) {
        const uint32_t* ah = AH + (mt * 16 + lr) * 36 + lc;
        const uint32_t* al = AL + (mt * 16 + lr) * 36 + lc;
        const uint32_t h0 = ah[32], h1 = ah[8 * 36 + 32];
        const uint32_t l0 = al[32], l1 = al[8 * 36 + 32];
#pragma unroll
        for (int ns = 0; ns < NS; ns++) {
            const int nb = n0 + ns * 8;
            const uint32_t p = BH[(nb + lr) * 36 + lc + 32];
            const uint32_t q = BL[(nb + lr) * 36 + lc + 32];
            mma8h(acc[ns], h0, h1, p);
            mma8h(acc[ns], l0, l1, p);
            mma8h(acc[ns], h0, h1, q);
        }
    }

    float ss = 0.f;
    const int r0 = mt * 16 + lr, rr = r0 + 8;
#pragma unroll
    for (int ns = 0; ns < NS; ns++) {
        const int col = n0 + ns * 8 + 2 * lc;
        if (EPI == 0) {
            uint32_t* cH = (uint32_t*)c0;
            uint32_t* cL = (uint32_t*)c1;
            const float b0v = aux[col], b1v = aux[col + 1];
            const int kw = (n0 >> 1) + 4 * ns + lc;
            uint32_t hw, lw;
            pack_hl(acc[ns][0] + b0v, acc[ns][1] + b1v, hw, lw);
            cH[r0 * 36 + kw] = hw; cL[r0 * 36 + kw] = lw;
            pack_hl(acc[ns][2] + b0v, acc[ns][3] + b1v, hw, lw);
            cH[rr * 36 + kw] = hw; cL[rr * 36 + kw] = lw;
        } else if (EPI == 1) {
            float* cS = (float*)c0;
            *(float2*)(cS + r0 * 72 + col) = make_float2(acc[ns][0] * scale, acc[ns][1] * scale);
            *(float2*)(cS + rr * 72 + col) = make_float2(acc[ns][2] * scale, acc[ns][3] * scale);
        } else if (EPI == 2) {
            float* o = (float*)c0;
            if (col < 64) {
                const float ga = aux[col], gb = aux[col + 1];
                o[r0 * DIM + col] = ga * acc[ns][0];
                o[r0 * DIM + col + 1] = gb * acc[ns][1];
                if (rr < S) {
                    o[rr * DIM + col] = ga * acc[ns][2];
                    o[rr * DIM + col + 1] = gb * acc[ns][3];
                }
            } else if (col == 64) {
                o[r0 * DIM + 64] = aux[64] * acc[ns][0];
                if (rr < S) o[rr * DIM + 64] = aux[64] * acc[ns][2];
            }
        } else {
            if (col < S) { const float d = acc[ns][0] - ((r0 == col) ? 1.f : 0.f); ss = fmaf(d, d, ss); }
            if (col + 1 < S) { const float d = acc[ns][1] - ((r0 == col + 1) ? 1.f : 0.f); ss = fmaf(d, d, ss); }
            if (rr < S) {
                if (col < S) { const float d = acc[ns][2] - ((rr == col) ? 1.f : 0.f); ss = fmaf(d, d, ss); }
                if (col + 1 < S) { const float d = acc[ns][3] - ((rr == col + 1) ? 1.f : 0.f); ss = fmaf(d, d, ss); }
            }
        }
    }
    return ss;
}

// 16-warp GEMM over N=72: groups 0..2 -> NS=2 (n0=g*16), group 3 -> NS=3 (48..71)
template <int EPI, bool K8>
__device__ __forceinline__ float wide_gemm(
    const uint32_t* AH, const uint32_t* AL, const uint32_t* BH, const uint32_t* BL,
    int mt, int g, void* c0, void* c1, const float* aux)
{
    if (g < 3) return mma_tile<EPI, 2, K8>(AH, AL, BH, BL, mt, g * 16, c0, c1, aux, 0.f);
    return mma_tile<EPI, 3, K8>(AH, AL, BH, BL, mt, 48, c0, c1, aux, 0.f);
}

__device__ __forceinline__ void softmax_pack(const float* __restrict__ sS,
                                             uint32_t* __restrict__ AHp,
                                             uint32_t* __restrict__ ALp) {
    const int w = threadIdx.x >> 5, lane = threadIdx.x & 31;
    const bool ok1 = (lane + 32) < S;
    for (int r = w; r < S; r += 32) {
        const float* row = sS + r * 72;
        const float v0 = row[lane];
        const float v1 = ok1 ? row[lane + 32] : -1e30f;
        float m = fmaxf(v0, v1);
#pragma unroll
        for (int off = 16; off; off >>= 1) m = fmaxf(m, __shfl_xor_sync(0xffffffffu, m, off));
        const float e0 = __expf(v0 - m);
        const float e1 = ok1 ? __expf(v1 - m) : 0.f;
        float s = e0 + e1;
#pragma unroll
        for (int off = 16; off; off >>= 1) s += __shfl_xor_sync(0xffffffffu, s, off);
        const float inv = 1.0f / s;
        const float p0 = e0 * inv, p1 = ok1 ? e1 * inv : 0.f;
        const float p0n = __shfl_down_sync(0xffffffffu, p0, 1);
        const float p1n = __shfl_down_sync(0xffffffffu, p1, 1);
        if ((lane & 1) == 0) {
            uint32_t hw, lw;
            pack_hl(p0, p0n, hw, lw);
            AHp[r * 36 + (lane >> 1)] = hw; ALp[r * 36 + (lane >> 1)] = lw;
            pack_hl(p1, p1n, hw, lw);
            AHp[r * 36 + (lane >> 1) + 16] = hw; ALp[r * 36 + (lane >> 1) + 16] = lw;
        }
    }
}

__device__ __forceinline__ void prefetch_wdir(int h, int d, uint32_t* sWH, uint32_t* sWL) {
    const int base = (h * 4 + 2 * d) * 2592;
    const float4* sh = (const float4*)(g_wh + base);
    const float4* sl = (const float4*)(g_wl + base);
    const uint32_t dh = s2u(sWH), dl = s2u(sWL);
    for (int j = threadIdx.x; j < 1296; j += NT) {
        cp16(dh + 16u * j, sh + j);
        cp16(dl + 16u * j, sl + j);
    }
    cp_commit();
}

__global__ void __launch_bounds__(NT, 1)
fused_kernel(const float* __restrict__ Fn, const float* __restrict__ Fr,
             const float* __restrict__ bq1, const float* __restrict__ bk1,
             const float* __restrict__ bq2, const float* __restrict__ bk2,
             float* __restrict__ out, float* __restrict__ out_loss)
{
    extern __shared__ uint32_t sm[];
    const int tid = threadIdx.x, b = blockIdx.x, w = tid >> 5;
    const int half = w >> 4;            // dual-GEMM split
    const int mt4 = w & 3;              // row tile
    const int gp = (w >> 2) & 3;        // wide-gemm col group (within half)
    const int qg = w >> 2;              // 0..7, logits/loss col group
    float* sS = (float*)(sm + W_SS);
    float* sBias = (float*)(sm + W_BIA);
    float* sG = (float*)(sm + W_G);
    float* swarp = (float*)(sm + W_WRP);
    int* sflag = (int*)(sm + W_FLG);

    {
        float4* z = (float4*)sm;
        const float4 z4 = make_float4(0.f, 0.f, 0.f, 0.f);
        for (int i = tid; i < SMEM_WORDS / 4; i += NT) z[i] = z4;
    }
    __syncthreads();
    prefetch_wdir(0, 0, sm + W_WH, sm + W_WL);

    const float* fn = Fn + (size_t)b * S * DIM;
    const float* fr = Fr + (size_t)b * S * DIM;
    for (int idx = tid; idx < S * 33; idx += NT) {
        const int r = idx / 33, kw = idx - r * 33;
        const int k0 = 2 * kw, k1 = k0 + 1;
        uint32_t hw, lw;
        pack_hl(fn[r * DIM + k0], (k1 < DIM) ? fn[r * DIM + k1] : 0.f, hw, lw);
        sm[W_FNH + r * 36 + kw] = hw; sm[W_FNL + r * 36 + kw] = lw;
        pack_hl(fr[r * DIM + k0], (k1 < DIM) ? fr[r * DIM + k1] : 0.f, hw, lw);
        sm[W_FRH + r * 36 + kw] = hw; sm[W_FRL + r * 36 + kw] = lw;
    }
    for (int idx = tid; idx < DIM * 31; idx += NT) {
        const int d = idx / 31, rw = idx - d * 31;
        const int r0i = 2 * rw, r1i = r0i + 1;
        uint32_t hw, lw;
        pack_hl(fn[r0i * DIM + d], fn[r1i * DIM + d], hw, lw);
        sm[W_TNH + d * 36 + rw] = hw; sm[W_TNL + d * 36 + rw] = lw;
        pack_hl(fr[r0i * DIM + d], fr[r1i * DIM + d], hw, lw);
        sm[W_TRH + d * 36 + rw] = hw; sm[W_TRL + d * 36 + rw] = lw;
    }
    {
        const float* bsrc[4] = { bq1, bk1, bq2, bk2 };
        for (int idx = tid; idx < 40 * DIM; idx += NT) {
            const int m = idx / DIM, o = idx - m * DIM;
            sBias[m * 72 + o] = bsrc[m & 3][(m >> 2) * DIM + o];
        }
    }
    if (tid < DIM) {
        const float gg = g_gate[b * DIM + tid];
        sG[tid] = gg; sG[72 + tid] = 1.0f - gg;
    }
    const float scale = rsqrtf((float)DIM);
    cp_wait0();
    __syncthreads();

    for (int h = 0; h < H; h++) {
        float* o1 = out + ((size_t)(b * H + h) * 124) * DIM;
        float* o2 = o1 + (size_t)S * DIM;

        // P1: dir1 dual projections (16 warps each)
        if (half == 0)
            wide_gemm<0, true>(sm + W_FNH, sm + W_FNL, sm + W_WH, sm + W_WL,
                               mt4, gp, sm + W_QH, sm + W_QL, sBias + (h * 4 + 0) * 72);
        else
            wide_gemm<0, true>(sm + W_FRH, sm + W_FRL, sm + W_WH + 2592, sm + W_WL + 2592,
                               mt4, gp, sm + W_KH, sm + W_KL, sBias + (h * 4 + 1) * 72);
        __syncthreads();

        // P2: prefetch dir2; logits1 (32 warps, NS=1); wait W
        prefetch_wdir(h, 1, sm + W_WH, sm + W_WL);
        mma_tile<1, 1, true>(sm + W_QH, sm + W_QL, sm + W_KH, sm + W_KL,
                             mt4, qg * 8, sS, 0, 0, scale);
        cp_wait0();
        __syncthreads();

        // P3: softmax1 + dir2 dual projections
        softmax_pack(sS, sm + W_A1H, sm + W_A1L);
        if (half == 0)
            wide_gemm<0, true>(sm + W_FRH, sm + W_FRL, sm + W_WH, sm + W_WL,
                               mt4, gp, sm + W_QH, sm + W_QL, sBias + (h * 4 + 2) * 72);
        else
            wide_gemm<0, true>(sm + W_FNH, sm + W_FNL, sm + W_WH + 2592, sm + W_WL + 2592,
                               mt4, gp, sm + W_KH, sm + W_KL, sBias + (h * 4 + 3) * 72);
        __syncthreads();

        // P4: prefetch next dir1; logits2
        if (h + 1 < H) prefetch_wdir(h + 1, 0, sm + W_WH, sm + W_WL);
        mma_tile<1, 1, true>(sm + W_QH, sm + W_QL, sm + W_KH, sm + W_KL,
                             mt4, qg * 8, sS, 0, 0, scale);
        __syncthreads();

        // P5: softmax2
        softmax_pack(sS, sm + W_A2H, sm + W_A2L);
        __syncthreads();

        // P6: loss gram (32 warps NS=1) + dual gated outputs; wait next W
        float ss = mma_tile<3, 1, false>(sm + W_A1H, sm + W_A1L, sm + W_A2H, sm + W_A2L,
                                         mt4, qg * 8, 0, 0, 0, 0.f);
        if (half == 0)
            wide_gemm<2, false>(sm + W_A1H, sm + W_A1L, sm + W_TRH, sm + W_TRL,
                                mt4, gp, o1, 0, sG);
        else
            wide_gemm<2, false>(sm + W_A2H, sm + W_A2L, sm + W_TNH, sm + W_TNL,
                                mt4, gp, o2, 0, sG + 72);
#pragma unroll
        for (int off = 16; off; off >>= 1) ss += __shfl_xor_sync(0xffffffffu, ss, off);
        if ((tid & 31) == 0) swarp[h * 32 + w] = ss;
        cp_wait0();
        __syncthreads();
    }

    if (tid < H) {
        float t = 0.f;
#pragma unroll
        for (int ww = 0; ww < 32; ww++) t += swarp[tid * 32 + ww];
        g_norms[b * H + tid] = sqrtf(t);
    }
    __threadfence();
    __syncthreads();
    if (tid == 0) *sflag = ((atomicAdd(&g_ctr, 1) % BSZ) == BSZ - 1) ? 1 : 0;
    __syncthreads();
    if (*sflag) {
        float s = 0.f;
        for (int i = tid; i < BSZ * H; i += NT) s += g_norms[i];
#pragma unroll
        for (int off = 16; off; off >>= 1) s += __shfl_xor_sync(0xffffffffu, s, off);
        if ((tid & 31) == 0) swarp[w] = s;
        __syncthreads();
        if (tid == 0) {
            float t = 0.f;
#pragma unroll
            for (int ww = 0; ww < 32; ww++) t += swarp[ww];
            *out_loss = t / (float)(BSZ * H);
        }
    }
}

extern "C" void kernel_launch(void* const* d_in, const int* in_sizes, int n_in,
                              void* d_out, int out_size)
{
    const float* Fn  = (const float*)d_in[0];
    const float* Fr  = (const float*)d_in[1];
    const float* Wq1 = (const float*)d_in[2];
    const float* bq1 = (const float*)d_in[3];
    const float* Wk1 = (const float*)d_in[4];
    const float* bk1 = (const float*)d_in[5];
    const float* Wq2 = (const float*)d_in[6];
    const float* bq2 = (const float*)d_in[7];
    const float* Wk2 = (const float*)d_in[8];
    const float* bk2 = (const float*)d_in[9];
    const float* Wg  = (const float*)d_in[10];
    const float* bg  = (const float*)d_in[11];
    float* out = (float*)d_out;

    prep_kernel<<<BSZ + 160, 256>>>(Fn, Fr, Wg, bg, Wq1, Wk1, Wq2, Wk2);
    const int smem_bytes = SMEM_WORDS * 4;
    cudaFuncSetAttribute(fused_kernel, cudaFuncAttributeMaxDynamicSharedMemorySize, smem_bytes);
    fused_kernel<<<BSZ, NT, smem_bytes>>>(Fn, Fr, bq1, bk1, bq2, bk2,
                                          out, out + (size_t)out_size - 1);
}

// round 14
// speedup vs baseline: 1.0635x; 1.0635x over previous
#include <cuda_runtime.h>
#include <cuda_fp16.h>
#include <cstdint>

#define BSZ 1024
#define S 62
#define DIM 65
#define H 10
#define NT 512

#define W_FNH 0
#define W_FNL 2304
#define W_FRH 4608
#define W_FRL 6912
#define W_TNH 9216
#define W_TNL 11808
#define W_TRH 14400
#define W_TRL 16992
#define W_WH  19584
#define W_WL  24768
#define W_QH  29952
#define W_QL  32256
#define W_KH  34560
#define W_KL  36864
#define W_A1H 39168
#define W_A1L 41472
#define W_A2H 43776
#define W_A2L 46080
#define W_SS  48384
#define W_BIA 52992
#define W_G   55872
#define W_WRP 56016
#define W_FNC 56180
#define W_FRC 56244
#define W_QC  56308
#define W_KC  56372
#define W_WC  56436
#define W_FLG 56580
#define SMEM_WORDS 56584

__device__ uint32_t g_wh[40 * 72 * 36];
__device__ uint32_t g_wl[40 * 72 * 36];
__device__ float    g_wc[40 * 72];
__device__ float    g_gate[BSZ * DIM];
__device__ float    g_norms[BSZ * H];
__device__ int      g_ctr;

__device__ __forceinline__ void cp16(uint32_t dst, const void* src) {
    asm volatile("cp.async.cg.shared.global [%0], [%1], 16;\n" :: "r"(dst), "l"(src));
}
__device__ __forceinline__ void cp_commit() { asm volatile("cp.async.commit_group;\n"); }
__device__ __forceinline__ void cp_wait0()  { asm volatile("cp.async.wait_group 0;\n"); }

__device__ __forceinline__ void pack_hl(float x, float y, uint32_t& hw, uint32_t& lw) {
    const __half hx = __float2half_rn(x), hy = __float2half_rn(y);
    __half2 h = __halves2half2(hx, hy);
    __half2 l = __halves2half2(__float2half_rn(x - __half2float(hx)),
                               __float2half_rn(y - __half2float(hy)));
    hw = *reinterpret_cast<uint32_t*>(&h);
    lw = *reinterpret_cast<uint32_t*>(&l);
}
__device__ __forceinline__ void mma16(float* c, uint32_t a0, uint32_t a1,
                                      uint32_t a2, uint32_t a3, uint32_t b0, uint32_t b1) {
    asm volatile("mma.sync.aligned.m16n8k16.row.col.f32.f16.f16.f32 "
                 "{%0,%1,%2,%3}, {%4,%5,%6,%7}, {%8,%9}, {%0,%1,%2,%3};\n"
                 : "+f"(c[0]), "+f"(c[1]), "+f"(c[2]), "+f"(c[3])
                 : "r"(a0), "r"(a1), "r"(a2), "r"(a3), "r"(b0), "r"(b1));
}
__device__ __forceinline__ void ldsm4(uint32_t& r0, uint32_t& r1, uint32_t& r2,
                                      uint32_t& r3, uint32_t a) {
    asm volatile("ldmatrix.sync.aligned.m8n8.x4.shared.b16 {%0,%1,%2,%3}, [%4];\n"
                 : "=r"(r0), "=r"(r1), "=r"(r2), "=r"(r3) : "r"(a));
}
__device__ __forceinline__ void ldsm2(uint32_t& r0, uint32_t& r1, uint32_t a) {
    asm volatile("ldmatrix.sync.aligned.m8n8.x2.shared.b16 {%0,%1}, [%2];\n"
                 : "=r"(r0), "=r"(r1) : "r"(a));
}
__device__ __forceinline__ uint32_t s2u(const void* p) {
    return (uint32_t)__cvta_generic_to_shared(p);
}

__global__ void prep_kernel(const float* __restrict__ Fn, const float* __restrict__ Fr,
                            const float* __restrict__ Wg, const float* __restrict__ bg,
                            const float* __restrict__ Wq1, const float* __restrict__ Wk1,
                            const float* __restrict__ Wq2, const float* __restrict__ Wk2) {
    const int t = threadIdx.x;
    if (blockIdx.x < BSZ) {
        __shared__ float mean[132];
        const int b = blockIdx.x;
        if (t < 2 * DIM) {
            const float* src = (t < DIM) ? (Fn + (size_t)b * S * DIM + t)
                                         : (Fr + (size_t)b * S * DIM + t - DIM);
            float s = 0.f;
            for (int i = 0; i < S; i++) s += src[i * DIM];
            mean[t] = s * (1.0f / (float)S);
        }
        __syncthreads();
        if (t < DIM) {
            float acc = bg[t];
            const float* wr = Wg + t * 2 * DIM;
#pragma unroll 10
            for (int c = 0; c < 2 * DIM; c++) acc = fmaf(wr[c], mean[c], acc);
            g_gate[b * DIM + t] = 1.0f / (1.0f + __expf(-acc));
        }
    } else {
        const float* srcs[4] = { Wq1, Wk1, Wq2, Wk2 };
        const int total = 40 * 72 * 36;
        for (int idx = (blockIdx.x - BSZ) * 256 + t; idx < total; idx += 160 * 256) {
            const int m = idx / (72 * 36);
            const int rem = idx - m * 72 * 36;
            const int n = rem / 36, kw = rem - n * 36;
            const float* src = srcs[m & 3] + (m >> 2) * DIM * DIM;
            const int k0 = 2 * kw, k1 = k0 + 1;
            const float v0 = (n < DIM && k0 < DIM) ? src[n * DIM + k0] : 0.f;
            const float v1 = (n < DIM && k1 < DIM) ? src[n * DIM + k1] : 0.f;
            uint32_t hw, lw;
            pack_hl(v0, v1, hw, lw);
            g_wh[idx] = hw; g_wl[idx] = lw;
        }
        for (int idx = (blockIdx.x - BSZ) * 256 + t; idx < 40 * 72; idx += 160 * 256) {
            const int m = idx / 72, n = idx - m * 72;
            g_wc[idx] = (n < DIM) ? srcs[m & 3][(m >> 2) * DIM * DIM + n * DIM + 64] : 0.f;
        }
    }
}

// A [m][kw], B [n][kw], stride 36 words. TERMS: 3 = hh+lh+hl, 2 = hh+lh.
// SIDE: epilogue adds aC[r]*bC[col] (k-element 64).
// EPI0: pack+bias -> planes (+qcOut fp32 col64); EPI1 scores*scale;
// EPI2 gmem gated; EPI3 loss sum.
template <int EPI, int NS, int TERMS, bool SIDE>
__device__ __forceinline__ float mma_tile(
    const uint32_t* __restrict__ AH, const uint32_t* __restrict__ AL,
    const uint32_t* __restrict__ BH, const uint32_t* __restrict__ BL,
    const float* __restrict__ aC, const float* __restrict__ bC,
    float* __restrict__ qcOut,
    const int mt, const int n0, void* c0, void* c1,
    const float* __restrict__ aux, const float scale)
{
    const int lane = threadIdx.x & 31, lr = lane >> 2, lc = lane & 3;
    float acc[NS][4];
#pragma unroll
    for (int ns = 0; ns < NS; ns++)
        acc[ns][0] = acc[ns][1] = acc[ns][2] = acc[ns][3] = 0.f;

    const int ar = lane & 15, ac4 = (lane >> 4) << 2;
    const uint32_t aH = s2u(AH) + (((mt * 16 + ar) * 36 + ac4) << 2);
    const uint32_t aL = s2u(AL) + (((mt * 16 + ar) * 36 + ac4) << 2);
    const int br = (lane & 7) | ((lane >> 4) << 3), bc4 = ((lane >> 3) & 1) << 2;
    const uint32_t bHp = s2u(BH) + (((n0 + br) * 36 + bc4) << 2);
    const uint32_t bLp = s2u(BL) + (((n0 + br) * 36 + bc4) << 2);
    const int xr = n0 + (NS & ~1) * 8 + (lane & 7), xc4 = ((lane >> 3) & 1) << 2;
    const uint32_t bHx = s2u(BH) + ((xr * 36 + xc4) << 2);
    const uint32_t bLx = s2u(BL) + ((xr * 36 + xc4) << 2);

#pragma unroll
    for (int s = 0; s < 4; s++) {
        const uint32_t kb = 32u * s;
        uint32_t a0, a1, a2, a3, e0, e1, e2, e3;
        ldsm4(a0, a1, a2, a3, aH + kb);
        ldsm4(e0, e1, e2, e3, aL + kb);
#pragma unroll
        for (int p = 0; p < NS / 2; p++) {
            uint32_t b0, b1, b2, b3;
            ldsm4(b0, b1, b2, b3, bHp + 2304u * p + kb);
            mma16(acc[2 * p], a0, a1, a2, a3, b0, b1);
            mma16(acc[2 * p], e0, e1, e2, e3, b0, b1);
            mma16(acc[2 * p + 1], a0, a1, a2, a3, b2, b3);
            mma16(acc[2 * p + 1], e0, e1, e2, e3, b2, b3);
            if (TERMS == 3) {
                uint32_t f0, f1, f2, f3;
                ldsm4(f0, f1, f2, f3, bLp + 2304u * p + kb);
                mma16(acc[2 * p], a0, a1, a2, a3, f0, f1);
                mma16(acc[2 * p + 1], a0, a1, a2, a3, f2, f3);
            }
        }
        if (NS & 1) {
            uint32_t x0, x1;
            ldsm2(x0, x1, bHx + kb);
            mma16(acc[NS - 1], a0, a1, a2, a3, x0, x1);
            mma16(acc[NS - 1], e0, e1, e2, e3, x0, x1);
            if (TERMS == 3) {
                uint32_t y0, y1;
                ldsm2(y0, y1, bLx + kb);
                mma16(acc[NS - 1], a0, a1, a2, a3, y0, y1);
            }
        }
    }

    float ss = 0.f;
    const int r0 = mt * 16 + lr, rr = r0 + 8;
    const float aC0 = SIDE ? aC[r0] : 0.f;
    const float aCr = SIDE ? aC[rr] : 0.f;
#pragma unroll
    for (int ns = 0; ns < NS; ns++) {
        const int col = n0 + ns * 8 + 2 * lc;
        const float bc0 = SIDE ? bC[col] : 0.f;
        const float bc1 = SIDE ? bC[col + 1] : 0.f;
        if (EPI == 0) {
            uint32_t* cH = (uint32_t*)c0;
            uint32_t* cL = (uint32_t*)c1;
            const float v0 = acc[ns][0] + aC0 * bc0 + aux[col];
            const float v1 = acc[ns][1] + aC0 * bc1 + aux[col + 1];
            const float w0 = acc[ns][2] + aCr * bc0 + aux[col];
            const float w1 = acc[ns][3] + aCr * bc1 + aux[col + 1];
            const int kw = (n0 >> 1) + 4 * ns + lc;
            uint32_t hw, lw;
            pack_hl(v0, v1, hw, lw);
            cH[r0 * 36 + kw] = hw; cL[r0 * 36 + kw] = lw;
            pack_hl(w0, w1, hw, lw);
            cH[rr * 36 + kw] = hw; cL[rr * 36 + kw] = lw;
            if (col == 64) { qcOut[r0] = v0; qcOut[rr] = w0; }
        } else if (EPI == 1) {
            float* cS = (float*)c0;
            *(float2*)(cS + r0 * 72 + col) =
                make_float2((acc[ns][0] + aC0 * bc0) * scale, (acc[ns][1] + aC0 * bc1) * scale);
            *(float2*)(cS + rr * 72 + col) =
                make_float2((acc[ns][2] + aCr * bc0) * scale, (acc[ns][3] + aCr * bc1) * scale);
        } else if (EPI == 2) {
            float* o = (float*)c0;
            if (col < 64) {
                const float ga = aux[col], gb = aux[col + 1];
                o[r0 * DIM + col] = ga * acc[ns][0];
                o[r0 * DIM + col + 1] = gb * acc[ns][1];
                if (rr < S) {
                    o[rr * DIM + col] = ga * acc[ns][2];
                    o[rr * DIM + col + 1] = gb * acc[ns][3];
                }
            } else if (col == 64) {
                o[r0 * DIM + 64] = aux[64] * acc[ns][0];
                if (rr < S) o[rr * DIM + 64] = aux[64] * acc[ns][2];
            }
        } else {
            if (col < S) { const float d = acc[ns][0] - ((r0 == col) ? 1.f : 0.f); ss = fmaf(d, d, ss); }
            if (col + 1 < S) { const float d = acc[ns][1] - ((r0 == col + 1) ? 1.f : 0.f); ss = fmaf(d, d, ss); }
            if (rr < S) {
                if (col < S) { const float d = acc[ns][2] - ((rr == col) ? 1.f : 0.f); ss = fmaf(d, d, ss); }
                if (col + 1 < S) { const float d = acc[ns][3] - ((rr == col + 1) ? 1.f : 0.f); ss = fmaf(d, d, ss); }
            }
        }
    }
    return ss;
}

// 8-warp GEMM over N=72: gp=0 -> cols 0..31 (NS=4), gp=1 -> cols 32..71 (NS=5)
template <int EPI, int TERMS, bool SIDE>
__device__ __forceinline__ float half_gemm(
    const uint32_t* AH, const uint32_t* AL, const uint32_t* BH, const uint32_t* BL,
    const float* aC, const float* bC, float* qcOut,
    int mt, int gp, void* c0, void* c1, const float* aux)
{
    if (gp == 0)
        return mma_tile<EPI, 4, TERMS, SIDE>(AH, AL, BH, BL, aC, bC, qcOut, mt, 0, c0, c1, aux, 0.f);
    return mma_tile<EPI, 5, TERMS, SIDE>(AH, AL, BH, BL, aC, bC, qcOut, mt, 32, c0, c1, aux, 0.f);
}

__device__ __forceinline__ void softmax_pack(const float* __restrict__ sS,
                                             uint32_t* __restrict__ AHp,
                                             uint32_t* __restrict__ ALp) {
    const int w = threadIdx.x >> 5, lane = threadIdx.x & 31;
    const bool ok1 = (lane + 32) < S;
    for (int r = w; r < S; r += 16) {
        const float* row = sS + r * 72;
        const float v0 = row[lane];
        const float v1 = ok1 ? row[lane + 32] : -1e30f;
        float m = fmaxf(v0, v1);
#pragma unroll
        for (int off = 16; off; off >>= 1) m = fmaxf(m, __shfl_xor_sync(0xffffffffu, m, off));
        const float e0 = __expf(v0 - m);
        const float e1 = ok1 ? __expf(v1 - m) : 0.f;
        float s = e0 + e1;
#pragma unroll
        for (int off = 16; off; off >>= 1) s += __shfl_xor_sync(0xffffffffu, s, off);
        const float inv = 1.0f / s;
        const float p0 = e0 * inv, p1 = ok1 ? e1 * inv : 0.f;
        const float p0n = __shfl_down_sync(0xffffffffu, p0, 1);
        const float p1n = __shfl_down_sync(0xffffffffu, p1, 1);
        if ((lane & 1) == 0) {
            uint32_t hw, lw;
            pack_hl(p0, p0n, hw, lw);
            AHp[r * 36 + (lane >> 1)] = hw; ALp[r * 36 + (lane >> 1)] = lw;
            pack_hl(p1, p1n, hw, lw);
            AHp[r * 36 + (lane >> 1) + 16] = hw; ALp[r * 36 + (lane >> 1) + 16] = lw;
        }
    }
}

__device__ __forceinline__ void prefetch_wdir(int h, int d, uint32_t* sm) {
    const int m0 = h * 4 + 2 * d;
    const float4* sh = (const float4*)(g_wh + m0 * 2592);
    const float4* sl = (const float4*)(g_wl + m0 * 2592);
    const uint32_t dh = s2u(sm + W_WH), dl = s2u(sm + W_WL);
    for (int j = threadIdx.x; j < 1296; j += NT) {
        cp16(dh + 16u * j, sh + j);
        cp16(dl + 16u * j, sl + j);
    }
    if (threadIdx.x < 36)
        cp16(s2u(sm + W_WC) + 16u * threadIdx.x, (const float4*)(g_wc + m0 * 72) + threadIdx.x);
    cp_commit();
}

__global__ void __launch_bounds__(NT, 1)
fused_kernel(const float* __restrict__ Fn, const float* __restrict__ Fr,
             const float* __restrict__ bq1, const float* __restrict__ bk1,
             const float* __restrict__ bq2, const float* __restrict__ bk2,
             float* __restrict__ out, float* __restrict__ out_loss)
{
    extern __shared__ uint32_t sm[];
    const int tid = threadIdx.x, b = blockIdx.x, w = tid >> 5;
    const int half = w >> 3, mt4 = w & 3, gp = (w >> 2) & 1, qg = w >> 2;
    float* sS = (float*)(sm + W_SS);
    float* sBias = (float*)(sm + W_BIA);
    float* sG = (float*)(sm + W_G);
    float* swarp = (float*)(sm + W_WRP);
    float* sFnC = (float*)(sm + W_FNC);
    float* sFrC = (float*)(sm + W_FRC);
    float* sQC = (float*)(sm + W_QC);
    float* sKC = (float*)(sm + W_KC);
    float* sWC = (float*)(sm + W_WC);
    int* sflag = (int*)(sm + W_FLG);

    {
        float4* z = (float4*)sm;
        const float4 z4 = make_float4(0.f, 0.f, 0.f, 0.f);
        for (int i = tid; i < SMEM_WORDS / 4; i += NT) z[i] = z4;
    }
    __syncthreads();
    prefetch_wdir(0, 0, sm);

    const float* fn = Fn + (size_t)b * S * DIM;
    const float* fr = Fr + (size_t)b * S * DIM;
    for (int idx = tid; idx < S * 32; idx += NT) {
        const int r = idx >> 5, kw = idx & 31;
        const int k0 = 2 * kw;
        uint32_t hw, lw;
        pack_hl(fn[r * DIM + k0], fn[r * DIM + k0 + 1], hw, lw);
        sm[W_FNH + r * 36 + kw] = hw; sm[W_FNL + r * 36 + kw] = lw;
        pack_hl(fr[r * DIM + k0], fr[r * DIM + k0 + 1], hw, lw);
        sm[W_FRH + r * 36 + kw] = hw; sm[W_FRL + r * 36 + kw] = lw;
    }
    for (int idx = tid; idx < DIM * 31; idx += NT) {
        const int d = idx / 31, rw = idx - d * 31;
        const int r0i = 2 * rw, r1i = r0i + 1;
        uint32_t hw, lw;
        pack_hl(fn[r0i * DIM + d], fn[r1i * DIM + d], hw, lw);
        sm[W_TNH + d * 36 + rw] = hw; sm[W_TNL + d * 36 + rw] = lw;
        pack_hl(fr[r0i * DIM + d], fr[r1i * DIM + d], hw, lw);
        sm[W_TRH + d * 36 + rw] = hw; sm[W_TRL + d * 36 + rw] = lw;
    }
    if (tid < 2 * S) {
        if (tid < S) sFnC[tid] = fn[tid * DIM + 64];
        else         sFrC[tid - S] = fr[(tid - S) * DIM + 64];
    }
    {
        const float* bsrc[4] = { bq1, bk1, bq2, bk2 };
        for (int idx = tid; idx < 40 * DIM; idx += NT) {
            const int m = idx / DIM, o = idx - m * DIM;
            sBias[m * 72 + o] = bsrc[m & 3][(m >> 2) * DIM + o];
        }
    }
    if (tid < DIM) {
        const float gg = g_gate[b * DIM + tid];
        sG[tid] = gg; sG[72 + tid] = 1.0f - gg;
    }
    const float scale = rsqrtf((float)DIM);
    cp_wait0();
    __syncthreads();

    for (int h = 0; h < H; h++) {
        float* o1 = out + ((size_t)(b * H + h) * 124) * DIM;
        float* o2 = o1 + (size_t)S * DIM;

        // P1: dir1 dual projections (Q = Fn@Wq1^T+b, K = Fr@Wk1^T+b)
        if (half == 0)
            half_gemm<0, 3, true>(sm + W_FNH, sm + W_FNL, sm + W_WH, sm + W_WL,
                                  sFnC, sWC, sQC, mt4, gp,
                                  sm + W_QH, sm + W_QL, sBias + (h * 4 + 0) * 72);
        else
            half_gemm<0, 3, true>(sm + W_FRH, sm + W_FRL, sm + W_WH + 2592, sm + W_WL + 2592,
                                  sFrC, sWC + 72, sKC, mt4, gp,
                                  sm + W_KH, sm + W_KL, sBias + (h * 4 + 1) * 72);
        __syncthreads();

        // P2: prefetch dir2; logits1; wait W
        prefetch_wdir(h, 1, sm);
        mma_tile<1, 2, 3, true>(sm + W_QH, sm + W_QL, sm + W_KH, sm + W_KL,
                                sQC, sKC, 0, mt4, qg * 16, sS, 0, 0, scale);
        cp_wait0();
        __syncthreads();

        // P3: softmax1 + dir2 dual projections
        softmax_pack(sS, sm + W_A1H, sm + W_A1L);
        if (half == 0)
            half_gemm<0, 3, true>(sm + W_FRH, sm + W_FRL, sm + W_WH, sm + W_WL,
                                  sFrC, sWC, sQC, mt4, gp,
                                  sm + W_QH, sm + W_QL, sBias + (h * 4 + 2) * 72);
        else
            half_gemm<0, 3, true>(sm + W_FNH, sm + W_FNL, sm + W_WH + 2592, sm + W_WL + 2592,
                                  sFnC, sWC + 72, sKC, mt4, gp,
                                  sm + W_KH, sm + W_KL, sBias + (h * 4 + 3) * 72);
        __syncthreads();

        // P4: prefetch next dir1; logits2
        if (h + 1 < H) prefetch_wdir(h + 1, 0, sm);
        mma_tile<1, 2, 3, true>(sm + W_QH, sm + W_QL, sm + W_KH, sm + W_KL,
                                sQC, sKC, 0, mt4, qg * 16, sS, 0, 0, scale);
        __syncthreads();

        // P5: softmax2
        softmax_pack(sS, sm + W_A2H, sm + W_A2L);
        __syncthreads();

        // P6: loss (3-term) + dual gated outputs (2-term); wait next W
        float ss = mma_tile<3, 2, 3, false>(sm + W_A1H, sm + W_A1L, sm + W_A2H, sm + W_A2L,
                                            0, 0, 0, mt4, qg * 16, 0, 0, 0, 0.f);
        if (half == 0)
            half_gemm<2, 2, false>(sm + W_A1H, sm + W_A1L, sm + W_TRH, sm + W_TRL,
                                   0, 0, 0, mt4, gp, o1, 0, sG);
        else
            half_gemm<2, 2, false>(sm + W_A2H, sm + W_A2L, sm + W_TNH, sm + W_TNL,
                                   0, 0, 0, mt4, gp, o2, 0, sG + 72);
#pragma unroll
        for (int off = 16; off; off >>= 1) ss += __shfl_xor_sync(0xffffffffu, ss, off);
        if ((tid & 31) == 0) swarp[h * 16 + w] = ss;
        cp_wait0();
        __syncthreads();
    }

    if (tid < H) {
        float t = 0.f;
#pragma unroll
        for (int ww = 0; ww < 16; ww++) t += swarp[tid * 16 + ww];
        g_norms[b * H + tid] = sqrtf(t);
    }
    __threadfence();
    __syncthreads();
    if (tid == 0) *sflag = ((atomicAdd(&g_ctr, 1) % BSZ) == BSZ - 1) ? 1 : 0;
    __syncthreads();
    if (*sflag) {
        float s = 0.f;
        for (int i = tid; i < BSZ * H; i += NT) s += g_norms[i];
#pragma unroll
        for (int off = 16; off; off >>= 1) s += __shfl_xor_sync(0xffffffffu, s, off);
        if ((tid & 31) == 0) swarp[w] = s;
        __syncthreads();
        if (tid == 0) {
            float t = 0.f;
#pragma unroll
            for (int ww = 0; ww < 16; ww++) t += swarp[ww];
            *out_loss = t / (float)(BSZ * H);
        }
    }
}

extern "C" void kernel_launch(void* const* d_in, const int* in_sizes, int n_in,
                              void* d_out, int out_size)
{
    const float* Fn  = (const float*)d_in[0];
    const float* Fr  = (const float*)d_in[1];
    const float* Wq1 = (const float*)d_in[2];
    const float* bq1 = (const float*)d_in[3];
    const float* Wk1 = (const float*)d_in[4];
    const float* bk1 = (const float*)d_in[5];
    const float* Wq2 = (const float*)d_in[6];
    const float* bq2 = (const float*)d_in[7];
    const float* Wk2 = (const float*)d_in[8];
    const float* bk2 = (const float*)d_in[9];
    const float* Wg  = (const float*)d_in[10];
    const float* bg  = (const float*)d_in[11];
    float* out = (float*)d_out;

    prep_kernel<<<BSZ + 160, 256>>>(Fn, Fr, Wg, bg, Wq1, Wk1, Wq2, Wk2);
    const int smem_bytes = SMEM_WORDS * 4;
    cudaFuncSetAttribute(fused_kernel, cudaFuncAttributeMaxDynamicSharedMemorySize, smem_bytes);
    fused_kernel<<<BSZ, NT, smem_bytes>>>(Fn, Fr, bq1, bk1, bq2, bk2,
                                          out, out + (size_t)out_size - 1);
}

// round 16
// speedup vs baseline: 1.2618x; 1.1864x over previous
#include <cuda_runtime.h>
#include <cuda_fp16.h>
#include <cstdint>

#define BSZ 1024
#define S 62
#define DIM 65
#define H 10
#define NT 512

#define W_FNH 0
#define W_FNL 2304
#define W_FRH 4608
#define W_FRL 6912
#define W_T1H 9216
#define W_T1L 11520
#define W_T2H 13824
#define W_T2L 16128
#define W_A1H 18432
#define W_A1L 20736
#define W_A2H 23040
#define W_A2L 25344
#define W_MH  27648
#define W_ML  32832
#define W_S1  38016
#define W_S2  42624
#define W_MC  47232
#define W_FNC 47520
#define W_FRC 47584
#define W_T1C 47648
#define W_T2C 47776
#define W_G   47904
#define W_WRP 48048
#define W_FLG 48208
#define SMEM_WORDS 48212

__device__ uint32_t g_mh[20 * 2592];
__device__ uint32_t g_ml[20 * 2592];
__device__ float    g_mc[20 * 144];
__device__ float    g_gate[BSZ * DIM];
__device__ float    g_norms[BSZ * H];
__device__ int      g_ctr;

__device__ __forceinline__ void cp16(uint32_t dst, const void* src) {
    asm volatile("cp.async.cg.shared.global [%0], [%1], 16;\n" :: "r"(dst), "l"(src));
}
__device__ __forceinline__ void cp_commit() { asm volatile("cp.async.commit_group;\n"); }
__device__ __forceinline__ void cp_wait0()  { asm volatile("cp.async.wait_group 0;\n"); }

__device__ __forceinline__ void pack_hl(float x, float y, uint32_t& hw, uint32_t& lw) {
    const __half hx = __float2half_rn(x), hy = __float2half_rn(y);
    __half2 h = __halves2half2(hx, hy);
    __half2 l = __halves2half2(__float2half_rn(x - __half2float(hx)),
                               __float2half_rn(y - __half2float(hy)));
    hw = *reinterpret_cast<uint32_t*>(&h);
    lw = *reinterpret_cast<uint32_t*>(&l);
}
__device__ __forceinline__ void mma16(float* c, uint32_t a0, uint32_t a1,
                                      uint32_t a2, uint32_t a3, uint32_t b0, uint32_t b1) {
    asm volatile("mma.sync.aligned.m16n8k16.row.col.f32.f16.f16.f32 "
                 "{%0,%1,%2,%3}, {%4,%5,%6,%7}, {%8,%9}, {%0,%1,%2,%3};\n"
                 : "+f"(c[0]), "+f"(c[1]), "+f"(c[2]), "+f"(c[3])
                 : "r"(a0), "r"(a1), "r"(a2), "r"(a3), "r"(b0), "r"(b1));
}
__device__ __forceinline__ void ldsm4(uint32_t& r0, uint32_t& r1, uint32_t& r2,
                                      uint32_t& r3, uint32_t a) {
    asm volatile("ldmatrix.sync.aligned.m8n8.x4.shared.b16 {%0,%1,%2,%3}, [%4];\n"
                 : "=r"(r0), "=r"(r1), "=r"(r2), "=r"(r3) : "r"(a));
}
__device__ __forceinline__ void ldsm2(uint32_t& r0, uint32_t& r1, uint32_t a) {
    asm volatile("ldmatrix.sync.aligned.m8n8.x2.shared.b16 {%0,%1}, [%2];\n"
                 : "=r"(r0), "=r"(r1) : "r"(a));
}
__device__ __forceinline__ void ldsm4t(uint32_t& r0, uint32_t& r1, uint32_t& r2,
                                       uint32_t& r3, uint32_t a) {
    asm volatile("ldmatrix.sync.aligned.m8n8.x4.trans.shared.b16 {%0,%1,%2,%3}, [%4];\n"
                 : "=r"(r0), "=r"(r1), "=r"(r2), "=r"(r3) : "r"(a));
}
__device__ __forceinline__ void ldsm2t(uint32_t& r0, uint32_t& r1, uint32_t a) {
    asm volatile("ldmatrix.sync.aligned.m8n8.x2.trans.shared.b16 {%0,%1}, [%2];\n"
                 : "=r"(r0), "=r"(r1) : "r"(a));
}
__device__ __forceinline__ uint32_t s2u(const void* p) {
    return (uint32_t)__cvta_generic_to_shared(p);
}

__global__ void prep_kernel(const float* __restrict__ Fn, const float* __restrict__ Fr,
                            const float* __restrict__ Wg, const float* __restrict__ bg,
                            const float* __restrict__ Wq1, const float* __restrict__ bq1,
                            const float* __restrict__ Wk1, const float* __restrict__ bk1,
                            const float* __restrict__ Wq2, const float* __restrict__ bq2,
                            const float* __restrict__ Wk2, const float* __restrict__ bk2) {
    const int t = threadIdx.x;
    if (blockIdx.x < BSZ) {
        __shared__ float mean[132];
        const int b = blockIdx.x;
        if (t < 2 * DIM) {
            const float* src = (t < DIM) ? (Fn + (size_t)b * S * DIM + t)
                                         : (Fr + (size_t)b * S * DIM + t - DIM);
            float s = 0.f;
            for (int i = 0; i < S; i++) s += src[i * DIM];
            mean[t] = s * (1.0f / (float)S);
        }
        __syncthreads();
        if (t < DIM) {
            float acc = bg[t];
            const float* wr = Wg + t * 2 * DIM;
#pragma unroll 10
            for (int c = 0; c < 2 * DIM; c++) acc = fmaf(wr[c], mean[c], acc);
            g_gate[b * DIM + t] = 1.0f / (1.0f + __expf(-acc));
        }
        return;
    }
    const int m = blockIdx.x - BSZ;
    const int h = m >> 1, d = m & 1;
    const float* Wq = d ? Wq2 : Wq1;  const float* bq = d ? bq2 : bq1;
    const float* Wk = d ? Wk2 : Wk1;  const float* bk = d ? bk2 : bk1;
    __shared__ float sq[DIM][66], sk[DIM][66];
    for (int i = t; i < DIM * DIM; i += 256) {
        const int o = i / DIM, c = i - o * DIM;
        sq[o][c] = Wq[h * DIM * DIM + i];
        sk[o][c] = Wk[h * DIM * DIM + i];
    }
    for (int o = t; o < DIM; o += 256) {
        sq[o][DIM] = bq[h * DIM + o];
        sk[o][DIM] = bk[h * DIM + o];
    }
    __syncthreads();
    for (int idx = t; idx < 66 * 33; idx += 256) {
        const int n = idx / 33, kp = idx - n * 33;
        if (kp < 32) {
            const int k0 = 2 * kp, k1 = k0 + 1;
            float s0 = 0.f, s1 = 0.f;
            for (int o = 0; o < DIM; o++) {
                const float wn = sk[o][n];
                s0 = fmaf(sq[o][k0], wn, s0);
                s1 = fmaf(sq[o][k1], wn, s1);
            }
            uint32_t hw, lw;
            pack_hl(s0, s1, hw, lw);
            g_mh[m * 2592 + n * 36 + kp] = hw;
            g_ml[m * 2592 + n * 36 + kp] = lw;
        } else {
            float s0 = 0.f, s1 = 0.f;
            for (int o = 0; o < DIM; o++) {
                const float wn = sk[o][n];
                s0 = fmaf(sq[o][64], wn, s0);
                s1 = fmaf(sq[o][65], wn, s1);
            }
            g_mc[m * 144 + n] = s0;
            g_mc[m * 144 + 72 + n] = s1;
        }
    }
}

// A [m][kw]; B [n][kw] non-trans, or (BT) B row-major [k][n] via ldmatrix.trans.
// TERMS 3 = AhBh+AlBh+AhBl, 2 = AhBh+AlBh.
// SIDE 1: acc += aC[r]*b1C[col] + b2C[col]; SIDE 2: acc += aC[r]*b1C[col] + aC2[r].
template <int EPI, int NS, int TERMS, int SIDE, bool BT>
__device__ __forceinline__ float mma_tile(
    const uint32_t* __restrict__ AH, const uint32_t* __restrict__ AL,
    const uint32_t* __restrict__ BH, const uint32_t* __restrict__ BL,
    const float* __restrict__ aC, const float* __restrict__ aC2,
    const float* __restrict__ b1C, const float* __restrict__ b2C,
    float* __restrict__ tC,
    const int mt, const int n0, void* c0, void* c1,
    const float* __restrict__ aux, const float scale)
{
    const int lane = threadIdx.x & 31, lr = lane >> 2, lc = lane & 3;
    float acc[NS][4];
#pragma unroll
    for (int ns = 0; ns < NS; ns++)
        acc[ns][0] = acc[ns][1] = acc[ns][2] = acc[ns][3] = 0.f;

    const int ar = lane & 15, ac4 = (lane >> 4) << 2;
    const uint32_t aH = s2u(AH) + (((mt * 16 + ar) * 36 + ac4) << 2);
    const uint32_t aL = s2u(AL) + (((mt * 16 + ar) * 36 + ac4) << 2);
    const int br = (lane & 7) | ((lane >> 4) << 3), bc4 = ((lane >> 3) & 1) << 2;
    const uint32_t bHp = s2u(BH) + (((n0 + br) * 36 + bc4) << 2);
    const uint32_t bLp = TERMS == 3 ? (s2u(BL) + (((n0 + br) * 36 + bc4) << 2)) : 0u;
    const int xr = n0 + (NS & ~1) * 8 + (lane & 7), xc4 = ((lane >> 3) & 1) << 2;
    const uint32_t bHx = s2u(BH) + ((xr * 36 + xc4) << 2);
    const uint32_t bLx = TERMS == 3 ? (s2u(BL) + ((xr * 36 + xc4) << 2)) : 0u;
    // trans B: stored [k][n]; addresses = k rows; matrices 2,3 at n+8 (+4 words)
    const int trow = (lane & 7) | (((lane >> 3) & 1) << 3);
    const uint32_t bT = s2u(BH) + ((trow * 36 + (n0 >> 1) + ((lane >> 4) << 2)) << 2);
    const uint32_t bTx = s2u(BH) + ((trow * 36 + ((n0 + (NS & ~1) * 8) >> 1)) << 2);

#pragma unroll
    for (int s = 0; s < 4; s++) {
        const uint32_t kb = 32u * s;       // non-trans: +8 kw words
        const uint32_t kt = 2304u * s;     // trans: +16 k rows (16*36*4 B)
        uint32_t a0, a1, a2, a3, e0, e1, e2, e3;
        ldsm4(a0, a1, a2, a3, aH + kb);
        ldsm4(e0, e1, e2, e3, aL + kb);
#pragma unroll
        for (int p = 0; p < NS / 2; p++) {
            uint32_t b0, b1, b2, b3;
            if (BT) ldsm4t(b0, b1, b2, b3, bT + kt + 32u * p);
            else    ldsm4(b0, b1, b2, b3, bHp + 2304u * p + kb);
            mma16(acc[2 * p], a0, a1, a2, a3, b0, b1);
            mma16(acc[2 * p], e0, e1, e2, e3, b0, b1);
            mma16(acc[2 * p + 1], a0, a1, a2, a3, b2, b3);
            mma16(acc[2 * p + 1], e0, e1, e2, e3, b2, b3);
            if (TERMS == 3) {
                uint32_t f0, f1, f2, f3;
                ldsm4(f0, f1, f2, f3, bLp + 2304u * p + kb);
                mma16(acc[2 * p], a0, a1, a2, a3, f0, f1);
                mma16(acc[2 * p + 1], a0, a1, a2, a3, f2, f3);
            }
        }
        if (NS & 1) {
            uint32_t x0, x1;
            if (BT) ldsm2t(x0, x1, bTx + kt);
            else    ldsm2(x0, x1, bHx + kb);
            mma16(acc[NS - 1], a0, a1, a2, a3, x0, x1);
            mma16(acc[NS - 1], e0, e1, e2, e3, x0, x1);
            if (TERMS == 3) {
                uint32_t y0, y1;
                ldsm2(y0, y1, bLx + kb);
                mma16(acc[NS - 1], a0, a1, a2, a3, y0, y1);
            }
        }
    }

    float ss = 0.f;
    const int r0 = mt * 16 + lr, rr = r0 + 8;
    const float s0a = (SIDE == 1 || SIDE == 2) ? aC[r0] : 0.f;
    const float sra = (SIDE == 1 || SIDE == 2) ? aC[rr] : 0.f;
    const float s0b = (SIDE == 2) ? aC2[r0] : 0.f;
    const float srb = (SIDE == 2) ? aC2[rr] : 0.f;
#pragma unroll
    for (int ns = 0; ns < NS; ns++) {
        const int col = n0 + ns * 8 + 2 * lc;
        float v0 = acc[ns][0], v1 = acc[ns][1], w0 = acc[ns][2], w1 = acc[ns][3];
        if (SIDE == 1) {
            v0 += s0a * b1C[col] + b2C[col];     v1 += s0a * b1C[col + 1] + b2C[col + 1];
            w0 += sra * b1C[col] + b2C[col];     w1 += sra * b1C[col + 1] + b2C[col + 1];
        } else if (SIDE == 2) {
            v0 += s0a * b1C[col] + s0b;          v1 += s0a * b1C[col + 1] + s0b;
            w0 += sra * b1C[col] + srb;          w1 += sra * b1C[col + 1] + srb;
        }
        if (EPI == 0) {
            uint32_t* cH = (uint32_t*)c0;
            uint32_t* cL = (uint32_t*)c1;
            const int kw = (n0 >> 1) + 4 * ns + lc;
            uint32_t hw, lw;
            pack_hl(v0, v1, hw, lw);
            cH[r0 * 36 + kw] = hw; cL[r0 * 36 + kw] = lw;
            pack_hl(w0, w1, hw, lw);
            cH[rr * 36 + kw] = hw; cL[rr * 36 + kw] = lw;
            if (col == 64) { tC[r0] = v0; tC[64 + r0] = v1; tC[rr] = w0; tC[64 + rr] = w1; }
        } else if (EPI == 1) {
            float* cS = (float*)c0;
            *(float2*)(cS + r0 * 72 + col) = make_float2(v0 * scale, v1 * scale);
            *(float2*)(cS + rr * 72 + col) = make_float2(w0 * scale, w1 * scale);
        } else if (EPI == 2) {
            float* o = (float*)c0;
            if (col < 64) {
                o[r0 * DIM + col] = aux[col] * v0;
                o[r0 * DIM + col + 1] = aux[col + 1] * v1;
                if (rr < S) {
                    o[rr * DIM + col] = aux[col] * w0;
                    o[rr * DIM + col + 1] = aux[col + 1] * w1;
                }
            } else if (col == 64) {
                o[r0 * DIM + 64] = aux[64] * v0;
                if (rr < S) o[rr * DIM + 64] = aux[64] * w0;
            }
        } else {
            if (col < S) { const float dd = v0 - ((r0 == col) ? 1.f : 0.f); ss = fmaf(dd, dd, ss); }
            if (col + 1 < S) { const float dd = v1 - ((r0 == col + 1) ? 1.f : 0.f); ss = fmaf(dd, dd, ss); }
            if (rr < S) {
                if (col < S) { const float dd = w0 - ((rr == col) ? 1.f : 0.f); ss = fmaf(dd, dd, ss); }
                if (col + 1 < S) { const float dd = w1 - ((rr == col + 1) ? 1.f : 0.f); ss = fmaf(dd, dd, ss); }
            }
        }
    }
    return ss;
}

__device__ __forceinline__ void softmax_pack(const float* __restrict__ sS,
                                             uint32_t* __restrict__ AHp,
                                             uint32_t* __restrict__ ALp,
                                             int r0, int rstep) {
    const int lane = threadIdx.x & 31;
    const bool ok1 = (lane + 32) < S;
    for (int r = r0; r < S; r += rstep) {
        const float* row = sS + r * 72;
        const float v0 = row[lane];
        const float v1 = ok1 ? row[lane + 32] : -1e30f;
        float m = fmaxf(v0, v1);
#pragma unroll
        for (int off = 16; off; off >>= 1) m = fmaxf(m, __shfl_xor_sync(0xffffffffu, m, off));
        const float e0 = __expf(v0 - m);
        const float e1 = ok1 ? __expf(v1 - m) : 0.f;
        float s = e0 + e1;
#pragma unroll
        for (int off = 16; off; off >>= 1) s += __shfl_xor_sync(0xffffffffu, s, off);
        const float inv = 1.0f / s;
        const float p0 = e0 * inv, p1 = ok1 ? e1 * inv : 0.f;
        const float p0n = __shfl_down_sync(0xffffffffu, p0, 1);
        const float p1n = __shfl_down_sync(0xffffffffu, p1, 1);
        if ((lane & 1) == 0) {
            uint32_t hw, lw;
            pack_hl(p0, p0n, hw, lw);
            AHp[r * 36 + (lane >> 1)] = hw; ALp[r * 36 + (lane >> 1)] = lw;
            pack_hl(p1, p1n, hw, lw);
            AHp[r * 36 + (lane >> 1) + 16] = hw; ALp[r * 36 + (lane >> 1) + 16] = lw;
        }
    }
}

__device__ __forceinline__ void prefetch_m(int h, uint32_t* sm) {
    const int m0 = 2 * h;
    const float4* sh = (const float4*)(g_mh + m0 * 2592);
    const float4* sl = (const float4*)(g_ml + m0 * 2592);
    const uint32_t dh = s2u(sm + W_MH), dl = s2u(sm + W_ML);
    for (int j = threadIdx.x; j < 1296; j += NT) {
        cp16(dh + 16u * j, sh + j);
        cp16(dl + 16u * j, sl + j);
    }
    if (threadIdx.x < 72)
        cp16(s2u(sm + W_MC) + 16u * threadIdx.x, (const float4*)(g_mc + m0 * 144) + threadIdx.x);
    cp_commit();
}

__global__ void __launch_bounds__(NT, 1)
fused_kernel(const float* __restrict__ Fn, const float* __restrict__ Fr,
             float* __restrict__ out, float* __restrict__ out_loss)
{
    extern __shared__ uint32_t sm[];
    const int tid = threadIdx.x, b = blockIdx.x, w = tid >> 5;
    const int half = w >> 3, mt4 = w & 3, gp = (w >> 2) & 1, qg = w >> 2;
    float* sS1 = (float*)(sm + W_S1);
    float* sS2 = (float*)(sm + W_S2);
    float* sMC = (float*)(sm + W_MC);
    float* sFnC = (float*)(sm + W_FNC);
    float* sFrC = (float*)(sm + W_FRC);
    float* sT1C = (float*)(sm + W_T1C);
    float* sT2C = (float*)(sm + W_T2C);
    float* sG = (float*)(sm + W_G);
    float* swarp = (float*)(sm + W_WRP);
    int* sflag = (int*)(sm + W_FLG);

    {
        float4* z = (float4*)sm;
        const float4 z4 = make_float4(0.f, 0.f, 0.f, 0.f);
        for (int i = tid; i < SMEM_WORDS / 4; i += NT) z[i] = z4;
    }
    __syncthreads();
    prefetch_m(0, sm);

    const float* fn = Fn + (size_t)b * S * DIM;
    const float* fr = Fr + (size_t)b * S * DIM;
    for (int idx = tid; idx < S * 32; idx += NT) {
        const int r = idx >> 5, kw = idx & 31;
        const int k0 = 2 * kw;
        uint32_t hw, lw;
        pack_hl(fn[r * DIM + k0], fn[r * DIM + k0 + 1], hw, lw);
        sm[W_FNH + r * 36 + kw] = hw; sm[W_FNL + r * 36 + kw] = lw;
        pack_hl(fr[r * DIM + k0], fr[r * DIM + k0 + 1], hw, lw);
        sm[W_FRH + r * 36 + kw] = hw; sm[W_FRL + r * 36 + kw] = lw;
    }
    if (tid < S) {
        const float a = fn[tid * DIM + 64], c = fr[tid * DIM + 64];
        uint32_t hw, lw;
        pack_hl(a, 0.f, hw, lw);
        sm[W_FNH + tid * 36 + 32] = hw; sm[W_FNL + tid * 36 + 32] = lw;
        pack_hl(c, 0.f, hw, lw);
        sm[W_FRH + tid * 36 + 32] = hw; sm[W_FRL + tid * 36 + 32] = lw;
        sFnC[tid] = a; sFrC[tid] = c;
    }
    if (tid < DIM) {
        const float gg = g_gate[b * DIM + tid];
        sG[tid] = gg; sG[72 + tid] = 1.0f - gg;
    }
    const float scale = rsqrtf((float)DIM);
    cp_wait0();
    __syncthreads();

    for (int h = 0; h < H; h++) {
        float* o1 = out + ((size_t)(b * H + h) * 124) * DIM;
        float* o2 = o1 + (size_t)S * DIM;

        // P1: T1 = Fn1 @ M~(dir1), T2 = Fr1 @ M~(dir2)   (dual 8/8)
        if (half == 0) {
            if (gp == 0)
                mma_tile<0, 4, 3, 1, false>(sm + W_FNH, sm + W_FNL, sm + W_MH, sm + W_ML,
                    sFnC, 0, sMC, sMC + 72, sT1C, mt4, 0, sm + W_T1H, sm + W_T1L, 0, 0.f);
            else
                mma_tile<0, 5, 3, 1, false>(sm + W_FNH, sm + W_FNL, sm + W_MH, sm + W_ML,
                    sFnC, 0, sMC, sMC + 72, sT1C, mt4, 32, sm + W_T1H, sm + W_T1L, 0, 0.f);
        } else {
            if (gp == 0)
                mma_tile<0, 4, 3, 1, false>(sm + W_FRH, sm + W_FRL, sm + W_MH + 2592, sm + W_ML + 2592,
                    sFrC, 0, sMC + 144, sMC + 216, sT2C, mt4, 0, sm + W_T2H, sm + W_T2L, 0, 0.f);
            else
                mma_tile<0, 5, 3, 1, false>(sm + W_FRH, sm + W_FRL, sm + W_MH + 2592, sm + W_ML + 2592,
                    sFrC, 0, sMC + 144, sMC + 216, sT2C, mt4, 32, sm + W_T2H, sm + W_T2L, 0, 0.f);
        }
        __syncthreads();

        // P2: prefetch next M~; S1 = T1@Fr1^T, S2 = T2@Fn1^T  (dual 8/8)
        if (h + 1 < H) prefetch_m(h + 1, sm);
        if (half == 0)
            mma_tile<1, 4, 3, 2, false>(sm + W_T1H, sm + W_T1L, sm + W_FRH, sm + W_FRL,
                sT1C, sT1C + 64, sFrC, 0, 0, mt4, gp * 32, sS1, 0, 0, scale);
        else
            mma_tile<1, 4, 3, 2, false>(sm + W_T2H, sm + W_T2L, sm + W_FNH, sm + W_FNL,
                sT2C, sT2C + 64, sFnC, 0, 0, mt4, gp * 32, sS2, 0, 0, scale);
        __syncthreads();

        // P3: dual softmax
        if (half == 0) softmax_pack(sS1, sm + W_A1H, sm + W_A1L, w & 7, 8);
        else           softmax_pack(sS2, sm + W_A2H, sm + W_A2L, w & 7, 8);
        __syncthreads();

        // P4: loss (all 16) + dual gated outputs (B via ldmatrix.trans, 2-term)
        float ss = mma_tile<3, 2, 3, 0, false>(sm + W_A1H, sm + W_A1L, sm + W_A2H, sm + W_A2L,
                                               0, 0, 0, 0, 0, mt4, qg * 16, 0, 0, 0, 0.f);
        if (half == 0) {
            if (gp == 0)
                mma_tile<2, 4, 2, 0, true>(sm + W_A1H, sm + W_A1L, sm + W_FRH, 0,
                    0, 0, 0, 0, 0, mt4, 0, o1, 0, sG, 0.f);
            else
                mma_tile<2, 5, 2, 0, true>(sm + W_A1H, sm + W_A1L, sm + W_FRH, 0,
                    0, 0, 0, 0, 0, mt4, 32, o1, 0, sG, 0.f);
        } else {
            if (gp == 0)
                mma_tile<2, 4, 2, 0, true>(sm + W_A2H, sm + W_A2L, sm + W_FNH, 0,
                    0, 0, 0, 0, 0, mt4, 0, o2, 0, sG + 72, 0.f);
            else
                mma_tile<2, 5, 2, 0, true>(sm + W_A2H, sm + W_A2L, sm + W_FNH, 0,
                    0, 0, 0, 0, 0, mt4, 32, o2, 0, sG + 72, 0.f);
        }
#pragma unroll
        for (int off = 16; off; off >>= 1) ss += __shfl_xor_sync(0xffffffffu, ss, off);
        if ((tid & 31) == 0) swarp[h * 16 + w] = ss;
        cp_wait0();
        __syncthreads();
    }

    if (tid < H) {
        float t = 0.f;
#pragma unroll
        for (int ww = 0; ww < 16; ww++) t += swarp[tid * 16 + ww];
        g_norms[b * H + tid] = sqrtf(t);
    }
    __threadfence();
    __syncthreads();
    if (tid == 0) *sflag = ((atomicAdd(&g_ctr, 1) % BSZ) == BSZ - 1) ? 1 : 0;
    __syncthreads();
    if (*sflag) {
        float s = 0.f;
        for (int i = tid; i < BSZ * H; i += NT) s += g_norms[i];
#pragma unroll
        for (int off = 16; off; off >>= 1) s += __shfl_xor_sync(0xffffffffu, s, off);
        if ((tid & 31) == 0) swarp[w] = s;
        __syncthreads();
        if (tid == 0) {
            float t = 0.f;
#pragma unroll
            for (int ww = 0; ww < 16; ww++) t += swarp[ww];
            *out_loss = t / (float)(BSZ * H);
        }
    }
}

extern "C" void kernel_launch(void* const* d_in, const int* in_sizes, int n_in,
                              void* d_out, int out_size)
{
    const float* Fn  = (const float*)d_in[0];
    const float* Fr  = (const float*)d_in[1];
    const float* Wq1 = (const float*)d_in[2];
    const float* bq1 = (const float*)d_in[3];
    const float* Wk1 = (const float*)d_in[4];
    const float* bk1 = (const float*)d_in[5];
    const float* Wq2 = (const float*)d_in[6];
    const float* bq2 = (const float*)d_in[7];
    const float* Wk2 = (const float*)d_in[8];
    const float* bk2 = (const float*)d_in[9];
    const float* Wg  = (const float*)d_in[10];
    const float* bg  = (const float*)d_in[11];
    float* out = (float*)d_out;

    prep_kernel<<<BSZ + 20, 256>>>(Fn, Fr, Wg, bg, Wq1, bq1, Wk1, bk1, Wq2, bq2, Wk2, bk2);
    const int smem_bytes = SMEM_WORDS * 4;
    cudaFuncSetAttribute(fused_kernel, cudaFuncAttributeMaxDynamicSharedMemorySize, smem_bytes);
    fused_kernel<<<BSZ, NT, smem_bytes>>>(Fn, Fr, out, out + (size_t)out_size - 1);
}

// round 17
// speedup vs baseline: 1.3450x; 1.0659x over previous
#include <cuda_runtime.h>
#include <cuda_fp16.h>
#include <cstdint>

#define BSZ 1024
#define S 62
#define DIM 65
#define H 10
#define NT 512

#define W_FNH 0
#define W_FNL 2304
#define W_FRH 4608
#define W_FRL 6912
#define W_T1H 9216
#define W_T1L 11520
#define W_T2H 13824
#define W_T2L 16128
#define W_A1H 18432
#define W_A1L 20736
#define W_A2H 23040
#define W_A2L 25344
#define W_MH  27648
#define W_ML  32832
#define W_S1  38016
#define W_S2  42624
#define W_MC  47232
#define W_FNC 47520
#define W_FRC 47584
#define W_T1C 47648
#define W_T2C 47776
#define W_G   47904
#define W_WRP 48048
#define W_FLG 48208
#define SMEM_WORDS 48212

__device__ uint32_t g_mh[20 * 2592];
__device__ uint32_t g_ml[20 * 2592];
__device__ float    g_mc[20 * 144];
__device__ float    g_gate[BSZ * DIM];
__device__ float    g_norms[BSZ * H];
__device__ int      g_ctr;

__device__ __forceinline__ void cp16(uint32_t dst, const void* src) {
    asm volatile("cp.async.cg.shared.global [%0], [%1], 16;\n" :: "r"(dst), "l"(src));
}
__device__ __forceinline__ void cp_commit() { asm volatile("cp.async.commit_group;\n"); }
__device__ __forceinline__ void cp_wait0()  { asm volatile("cp.async.wait_group 0;\n"); }

__device__ __forceinline__ void pack_hl(float x, float y, uint32_t& hw, uint32_t& lw) {
    const __half hx = __float2half_rn(x), hy = __float2half_rn(y);
    __half2 h = __halves2half2(hx, hy);
    __half2 l = __halves2half2(__float2half_rn(x - __half2float(hx)),
                               __float2half_rn(y - __half2float(hy)));
    hw = *reinterpret_cast<uint32_t*>(&h);
    lw = *reinterpret_cast<uint32_t*>(&l);
}
__device__ __forceinline__ void mma16(float* c, uint32_t a0, uint32_t a1,
                                      uint32_t a2, uint32_t a3, uint32_t b0, uint32_t b1) {
    asm volatile("mma.sync.aligned.m16n8k16.row.col.f32.f16.f16.f32 "
                 "{%0,%1,%2,%3}, {%4,%5,%6,%7}, {%8,%9}, {%0,%1,%2,%3};\n"
                 : "+f"(c[0]), "+f"(c[1]), "+f"(c[2]), "+f"(c[3])
                 : "r"(a0), "r"(a1), "r"(a2), "r"(a3), "r"(b0), "r"(b1));
}
__device__ __forceinline__ void ldsm4(uint32_t& r0, uint32_t& r1, uint32_t& r2,
                                      uint32_t& r3, uint32_t a) {
    asm volatile("ldmatrix.sync.aligned.m8n8.x4.shared.b16 {%0,%1,%2,%3}, [%4];\n"
                 : "=r"(r0), "=r"(r1), "=r"(r2), "=r"(r3) : "r"(a));
}
__device__ __forceinline__ void ldsm2(uint32_t& r0, uint32_t& r1, uint32_t a) {
    asm volatile("ldmatrix.sync.aligned.m8n8.x2.shared.b16 {%0,%1}, [%2];\n"
                 : "=r"(r0), "=r"(r1) : "r"(a));
}
__device__ __forceinline__ void ldsm4t(uint32_t& r0, uint32_t& r1, uint32_t& r2,
                                       uint32_t& r3, uint32_t a) {
    asm volatile("ldmatrix.sync.aligned.m8n8.x4.trans.shared.b16 {%0,%1,%2,%3}, [%4];\n"
                 : "=r"(r0), "=r"(r1), "=r"(r2), "=r"(r3) : "r"(a));
}
__device__ __forceinline__ void ldsm2t(uint32_t& r0, uint32_t& r1, uint32_t a) {
    asm volatile("ldmatrix.sync.aligned.m8n8.x2.trans.shared.b16 {%0,%1}, [%2];\n"
                 : "=r"(r0), "=r"(r1) : "r"(a));
}
__device__ __forceinline__ uint32_t s2u(const void* p) {
    return (uint32_t)__cvta_generic_to_shared(p);
}

__global__ void prep_kernel(const float* __restrict__ Fn, const float* __restrict__ Fr,
                            const float* __restrict__ Wg, const float* __restrict__ bg,
                            const float* __restrict__ Wq1, const float* __restrict__ bq1,
                            const float* __restrict__ Wk1, const float* __restrict__ bk1,
                            const float* __restrict__ Wq2, const float* __restrict__ bq2,
                            const float* __restrict__ Wk2, const float* __restrict__ bk2) {
    const int t = threadIdx.x;
    if (blockIdx.x < BSZ) {
        __shared__ float mean[132];
        const int b = blockIdx.x;
        if (t < 2 * DIM) {
            const float* src = (t < DIM) ? (Fn + (size_t)b * S * DIM + t)
                                         : (Fr + (size_t)b * S * DIM + t - DIM);
            float s = 0.f;
            for (int i = 0; i < S; i++) s += src[i * DIM];
            mean[t] = s * (1.0f / (float)S);
        }
        __syncthreads();
        if (t < DIM) {
            float acc = bg[t];
            const float* wr = Wg + t * 2 * DIM;
#pragma unroll 10
            for (int c = 0; c < 2 * DIM; c++) acc = fmaf(wr[c], mean[c], acc);
            g_gate[b * DIM + t] = 1.0f / (1.0f + __expf(-acc));
        }
        return;
    }
    const int m = blockIdx.x - BSZ;
    const int h = m >> 1, d = m & 1;
    const float* Wq = d ? Wq2 : Wq1;  const float* bq = d ? bq2 : bq1;
    const float* Wk = d ? Wk2 : Wk1;  const float* bk = d ? bk2 : bk1;
    __shared__ float sq[DIM][66], sk[DIM][66];
    for (int i = t; i < DIM * DIM; i += 256) {
        const int o = i / DIM, c = i - o * DIM;
        sq[o][c] = Wq[h * DIM * DIM + i];
        sk[o][c] = Wk[h * DIM * DIM + i];
    }
    for (int o = t; o < DIM; o += 256) {
        sq[o][DIM] = bq[h * DIM + o];
        sk[o][DIM] = bk[h * DIM + o];
    }
    __syncthreads();
    for (int idx = t; idx < 66 * 33; idx += 256) {
        const int n = idx / 33, kp = idx - n * 33;
        if (kp < 32) {
            const int k0 = 2 * kp, k1 = k0 + 1;
            float s0 = 0.f, s1 = 0.f;
            for (int o = 0; o < DIM; o++) {
                const float wn = sk[o][n];
                s0 = fmaf(sq[o][k0], wn, s0);
                s1 = fmaf(sq[o][k1], wn, s1);
            }
            uint32_t hw, lw;
            pack_hl(s0, s1, hw, lw);
            g_mh[m * 2592 + n * 36 + kp] = hw;
            g_ml[m * 2592 + n * 36 + kp] = lw;
        } else {
            float s0 = 0.f, s1 = 0.f;
            for (int o = 0; o < DIM; o++) {
                const float wn = sk[o][n];
                s0 = fmaf(sq[o][64], wn, s0);
                s1 = fmaf(sq[o][65], wn, s1);
            }
            g_mc[m * 144 + n] = s0;
            g_mc[m * 144 + 72 + n] = s1;
        }
    }
}

template <int EPI, int NS, int TERMS, int SIDE, bool BT>
__device__ __forceinline__ float mma_tile(
    const uint32_t* __restrict__ AH, const uint32_t* __restrict__ AL,
    const uint32_t* __restrict__ BH, const uint32_t* __restrict__ BL,
    const float* __restrict__ aC, const float* __restrict__ aC2,
    const float* __restrict__ b1C, const float* __restrict__ b2C,
    float* __restrict__ tC,
    const int mt, const int n0, void* c0, void* c1,
    const float* __restrict__ aux, const float scale)
{
    const int lane = threadIdx.x & 31, lr = lane >> 2, lc = lane & 3;
    float acc[NS][4];
#pragma unroll
    for (int ns = 0; ns < NS; ns++)
        acc[ns][0] = acc[ns][1] = acc[ns][2] = acc[ns][3] = 0.f;

    const int ar = lane & 15, ac4 = (lane >> 4) << 2;
    const uint32_t aH = s2u(AH) + (((mt * 16 + ar) * 36 + ac4) << 2);
    const uint32_t aL = s2u(AL) + (((mt * 16 + ar) * 36 + ac4) << 2);
    const int br = (lane & 7) | ((lane >> 4) << 3), bc4 = ((lane >> 3) & 1) << 2;
    const uint32_t bHp = s2u(BH) + (((n0 + br) * 36 + bc4) << 2);
    const uint32_t bLp = TERMS == 3 ? (s2u(BL) + (((n0 + br) * 36 + bc4) << 2)) : 0u;
    const int xr = n0 + (NS & ~1) * 8 + (lane & 7), xc4 = ((lane >> 3) & 1) << 2;
    const uint32_t bHx = s2u(BH) + ((xr * 36 + xc4) << 2);
    const uint32_t bLx = TERMS == 3 ? (s2u(BL) + ((xr * 36 + xc4) << 2)) : 0u;
    const int trow = (lane & 7) | (((lane >> 3) & 1) << 3);
    const uint32_t bT = s2u(BH) + ((trow * 36 + (n0 >> 1) + ((lane >> 4) << 2)) << 2);
    const uint32_t bTx = s2u(BH) + ((trow * 36 + ((n0 + (NS & ~1) * 8) >> 1)) << 2);

#pragma unroll
    for (int s = 0; s < 4; s++) {
        const uint32_t kb = 32u * s;
        const uint32_t kt = 2304u * s;
        uint32_t a0, a1, a2, a3, e0, e1, e2, e3;
        ldsm4(a0, a1, a2, a3, aH + kb);
        ldsm4(e0, e1, e2, e3, aL + kb);
#pragma unroll
        for (int p = 0; p < NS / 2; p++) {
            uint32_t b0, b1, b2, b3;
            if (BT) ldsm4t(b0, b1, b2, b3, bT + kt + 32u * p);
            else    ldsm4(b0, b1, b2, b3, bHp + 2304u * p + kb);
            mma16(acc[2 * p], a0, a1, a2, a3, b0, b1);
            mma16(acc[2 * p], e0, e1, e2, e3, b0, b1);
            mma16(acc[2 * p + 1], a0, a1, a2, a3, b2, b3);
            mma16(acc[2 * p + 1], e0, e1, e2, e3, b2, b3);
            if (TERMS == 3) {
                uint32_t f0, f1, f2, f3;
                ldsm4(f0, f1, f2, f3, bLp + 2304u * p + kb);
                mma16(acc[2 * p], a0, a1, a2, a3, f0, f1);
                mma16(acc[2 * p + 1], a0, a1, a2, a3, f2, f3);
            }
        }
        if (NS & 1) {
            uint32_t x0, x1;
            if (BT) ldsm2t(x0, x1, bTx + kt);
            else    ldsm2(x0, x1, bHx + kb);
            mma16(acc[NS - 1], a0, a1, a2, a3, x0, x1);
            mma16(acc[NS - 1], e0, e1, e2, e3, x0, x1);
            if (TERMS == 3) {
                uint32_t y0, y1;
                ldsm2(y0, y1, bLx + kb);
                mma16(acc[NS - 1], a0, a1, a2, a3, y0, y1);
            }
        }
    }

    float ss = 0.f;
    const int r0 = mt * 16 + lr, rr = r0 + 8;
    const float s0a = (SIDE == 1 || SIDE == 2) ? aC[r0] : 0.f;
    const float sra = (SIDE == 1 || SIDE == 2) ? aC[rr] : 0.f;
    const float s0b = (SIDE == 2) ? aC2[r0] : 0.f;
    const float srb = (SIDE == 2) ? aC2[rr] : 0.f;
#pragma unroll
    for (int ns = 0; ns < NS; ns++) {
        const int col = n0 + ns * 8 + 2 * lc;
        float v0 = acc[ns][0], v1 = acc[ns][1], w0 = acc[ns][2], w1 = acc[ns][3];
        if (SIDE == 1) {
            v0 += s0a * b1C[col] + b2C[col];     v1 += s0a * b1C[col + 1] + b2C[col + 1];
            w0 += sra * b1C[col] + b2C[col];     w1 += sra * b1C[col + 1] + b2C[col + 1];
        } else if (SIDE == 2) {
            v0 += s0a * b1C[col] + s0b;          v1 += s0a * b1C[col + 1] + s0b;
            w0 += sra * b1C[col] + srb;          w1 += sra * b1C[col + 1] + srb;
        }
        if (EPI == 0) {
            uint32_t* cH = (uint32_t*)c0;
            uint32_t* cL = (uint32_t*)c1;
            const int kw = (n0 >> 1) + 4 * ns + lc;
            uint32_t hw, lw;
            pack_hl(v0, v1, hw, lw);
            cH[r0 * 36 + kw] = hw; cL[r0 * 36 + kw] = lw;
            pack_hl(w0, w1, hw, lw);
            cH[rr * 36 + kw] = hw; cL[rr * 36 + kw] = lw;
            if (col == 64) { tC[r0] = v0; tC[64 + r0] = v1; tC[rr] = w0; tC[64 + rr] = w1; }
        } else if (EPI == 1) {
            float* cS = (float*)c0;
            *(float2*)(cS + r0 * 72 + col) = make_float2(v0 * scale, v1 * scale);
            *(float2*)(cS + rr * 72 + col) = make_float2(w0 * scale, w1 * scale);
        } else if (EPI == 2) {
            float* o = (float*)c0;
            if (col < 64) {
                o[r0 * DIM + col] = aux[col] * v0;
                o[r0 * DIM + col + 1] = aux[col + 1] * v1;
                if (rr < S) {
                    o[rr * DIM + col] = aux[col] * w0;
                    o[rr * DIM + col + 1] = aux[col + 1] * w1;
                }
            } else if (col == 64) {
                o[r0 * DIM + 64] = aux[64] * v0;
                if (rr < S) o[rr * DIM + 64] = aux[64] * w0;
            }
        } else {
            if (col < S) { const float dd = v0 - ((r0 == col) ? 1.f : 0.f); ss = fmaf(dd, dd, ss); }
            if (col + 1 < S) { const float dd = v1 - ((r0 == col + 1) ? 1.f : 0.f); ss = fmaf(dd, dd, ss); }
            if (rr < S) {
                if (col < S) { const float dd = w0 - ((rr == col) ? 1.f : 0.f); ss = fmaf(dd, dd, ss); }
                if (col + 1 < S) { const float dd = w1 - ((rr == col + 1) ? 1.f : 0.f); ss = fmaf(dd, dd, ss); }
            }
        }
    }
    return ss;
}

__device__ __forceinline__ void softmax_pack(const float* __restrict__ sS,
                                             uint32_t* __restrict__ AHp,
                                             uint32_t* __restrict__ ALp,
                                             int r0, int rstep) {
    const int lane = threadIdx.x & 31;
    const bool ok1 = (lane + 32) < S;
    for (int r = r0; r < S; r += rstep) {
        const float* row = sS + r * 72;
        const float v0 = row[lane];
        const float v1 = ok1 ? row[lane + 32] : -1e30f;
        float m = fmaxf(v0, v1);
#pragma unroll
        for (int off = 16; off; off >>= 1) m = fmaxf(m, __shfl_xor_sync(0xffffffffu, m, off));
        const float e0 = __expf(v0 - m);
        const float e1 = ok1 ? __expf(v1 - m) : 0.f;
        float s = e0 + e1;
#pragma unroll
        for (int off = 16; off; off >>= 1) s += __shfl_xor_sync(0xffffffffu, s, off);
        const float inv = 1.0f / s;
        const float p0 = e0 * inv, p1 = ok1 ? e1 * inv : 0.f;
        const float p0n = __shfl_down_sync(0xffffffffu, p0, 1);
        const float p1n = __shfl_down_sync(0xffffffffu, p1, 1);
        if ((lane & 1) == 0) {
            uint32_t hw, lw;
            pack_hl(p0, p0n, hw, lw);
            AHp[r * 36 + (lane >> 1)] = hw; ALp[r * 36 + (lane >> 1)] = lw;
            pack_hl(p1, p1n, hw, lw);
            AHp[r * 36 + (lane >> 1) + 16] = hw; ALp[r * 36 + (lane >> 1) + 16] = lw;
        }
    }
}

__device__ __forceinline__ void prefetch_m(int h, uint32_t* sm) {
    const int m0 = 2 * h;
    const float4* sh = (const float4*)(g_mh + m0 * 2592);
    const float4* sl = (const float4*)(g_ml + m0 * 2592);
    const uint32_t dh = s2u(sm + W_MH), dl = s2u(sm + W_ML);
    for (int j = threadIdx.x; j < 1296; j += NT) {
        cp16(dh + 16u * j, sh + j);
        cp16(dl + 16u * j, sl + j);
    }
    if (threadIdx.x < 72)
        cp16(s2u(sm + W_MC) + 16u * threadIdx.x, (const float4*)(g_mc + m0 * 144) + threadIdx.x);
    cp_commit();
}

__global__ void __launch_bounds__(NT, 1)
fused_kernel(const float* __restrict__ Fn, const float* __restrict__ Fr,
             float* __restrict__ out, float* __restrict__ out_loss)
{
    extern __shared__ uint32_t sm[];
    const int tid = threadIdx.x, b = blockIdx.x, w = tid >> 5;
    const int half = w >> 3, mt4 = w & 3, gp = (w >> 2) & 1, qg = w >> 2;
    float* sS1 = (float*)(sm + W_S1);
    float* sS2 = (float*)(sm + W_S2);
    float* sMC = (float*)(sm + W_MC);
    float* sFnC = (float*)(sm + W_FNC);
    float* sFrC = (float*)(sm + W_FRC);
    float* sT1C = (float*)(sm + W_T1C);
    float* sT2C = (float*)(sm + W_T2C);
    float* sG = (float*)(sm + W_G);
    float* swarp = (float*)(sm + W_WRP);
    int* sflag = (int*)(sm + W_FLG);

    {
        float4* z = (float4*)sm;
        const float4 z4 = make_float4(0.f, 0.f, 0.f, 0.f);
        for (int i = tid; i < SMEM_WORDS / 4; i += NT) z[i] = z4;
    }
    __syncthreads();
    prefetch_m(0, sm);

    const float* fn = Fn + (size_t)b * S * DIM;
    const float* fr = Fr + (size_t)b * S * DIM;
    for (int idx = tid; idx < S * 32; idx += NT) {
        const int r = idx >> 5, kw = idx & 31;
        const int k0 = 2 * kw;
        uint32_t hw, lw;
        pack_hl(fn[r * DIM + k0], fn[r * DIM + k0 + 1], hw, lw);
        sm[W_FNH + r * 36 + kw] = hw; sm[W_FNL + r * 36 + kw] = lw;
        pack_hl(fr[r * DIM + k0], fr[r * DIM + k0 + 1], hw, lw);
        sm[W_FRH + r * 36 + kw] = hw; sm[W_FRL + r * 36 + kw] = lw;
    }
    if (tid < S) {
        const float a = fn[tid * DIM + 64], c = fr[tid * DIM + 64];
        uint32_t hw, lw;
        pack_hl(a, 0.f, hw, lw);
        sm[W_FNH + tid * 36 + 32] = hw; sm[W_FNL + tid * 36 + 32] = lw;
        pack_hl(c, 0.f, hw, lw);
        sm[W_FRH + tid * 36 + 32] = hw; sm[W_FRL + tid * 36 + 32] = lw;
        sFnC[tid] = a; sFrC[tid] = c;
    }
    if (tid < DIM) {
        const float gg = g_gate[b * DIM + tid];
        sG[tid] = gg; sG[72 + tid] = 1.0f - gg;
    }
    const float scale = rsqrtf((float)DIM);
    cp_wait0();
    __syncthreads();

    // P1(h'): T = F1 @ M~, dual halves (reads current M slot)
#define DO_P1()                                                                        \
    if (half == 0) {                                                                   \
        if (gp == 0)                                                                   \
            mma_tile<0, 4, 3, 1, false>(sm + W_FNH, sm + W_FNL, sm + W_MH, sm + W_ML,  \
                sFnC, 0, sMC, sMC + 72, sT1C, mt4, 0, sm + W_T1H, sm + W_T1L, 0, 0.f); \
        else                                                                           \
            mma_tile<0, 5, 3, 1, false>(sm + W_FNH, sm + W_FNL, sm + W_MH, sm + W_ML,  \
                sFnC, 0, sMC, sMC + 72, sT1C, mt4, 32, sm + W_T1H, sm + W_T1L, 0, 0.f);\
    } else {                                                                           \
        if (gp == 0)                                                                   \
            mma_tile<0, 4, 3, 1, false>(sm + W_FRH, sm + W_FRL, sm + W_MH + 2592,      \
                sm + W_ML + 2592, sFrC, 0, sMC + 144, sMC + 216, sT2C, mt4, 0,         \
                sm + W_T2H, sm + W_T2L, 0, 0.f);                                       \
        else                                                                           \
            mma_tile<0, 5, 3, 1, false>(sm + W_FRH, sm + W_FRL, sm + W_MH + 2592,      \
                sm + W_ML + 2592, sFrC, 0, sMC + 144, sMC + 216, sT2C, mt4, 32,        \
                sm + W_T2H, sm + W_T2L, 0, 0.f);                                       \
    }

    // P2(h'): S = T @ F1^T, dual halves
#define DO_P2()                                                                        \
    if (half == 0)                                                                     \
        mma_tile<1, 4, 3, 2, false>(sm + W_T1H, sm + W_T1L, sm + W_FRH, sm + W_FRL,    \
            sT1C, sT1C + 64, sFrC, 0, 0, mt4, gp * 32, sS1, 0, 0, scale);              \
    else                                                                               \
        mma_tile<1, 4, 3, 2, false>(sm + W_T2H, sm + W_T2L, sm + W_FNH, sm + W_FNL,    \
            sT2C, sT2C + 64, sFnC, 0, 0, mt4, gp * 32, sS2, 0, 0, scale);

    // ---- prologue: T(0), then S(0) ----
    DO_P1();
    __syncthreads();
    prefetch_m(1, sm);
    DO_P2();
    cp_wait0();
    __syncthreads();

    for (int h = 0; h < H; h++) {
        float* o1 = out + ((size_t)(b * H + h) * 124) * DIM;
        float* o2 = o1 + (size_t)S * DIM;

        // Phase B(h): softmax(h) both dirs (16 warps), then P1(h+1)
        softmax_pack(sS1, sm + W_A1H, sm + W_A1L, w, 16);
        softmax_pack(sS2, sm + W_A2H, sm + W_A2L, w, 16);
        if (h + 1 < H) { DO_P1(); }   // reads M(h+1), writes T(h+1)
        __syncthreads();

        // Phase C(h): prefetch M(h+2); loss(h) + outputs(h) + P2(h+1)
        if (h + 2 < H) prefetch_m(h + 2, sm);
        float ss = mma_tile<3, 2, 3, 0, false>(sm + W_A1H, sm + W_A1L, sm + W_A2H, sm + W_A2L,
                                               0, 0, 0, 0, 0, mt4, qg * 16, 0, 0, 0, 0.f);
        if (half == 0) {
            if (gp == 0)
                mma_tile<2, 4, 2, 0, true>(sm + W_A1H, sm + W_A1L, sm + W_FRH, 0,
                    0, 0, 0, 0, 0, mt4, 0, o1, 0, sG, 0.f);
            else
                mma_tile<2, 5, 2, 0, true>(sm + W_A1H, sm + W_A1L, sm + W_FRH, 0,
                    0, 0, 0, 0, 0, mt4, 32, o1, 0, sG, 0.f);
        } else {
            if (gp == 0)
                mma_tile<2, 4, 2, 0, true>(sm + W_A2H, sm + W_A2L, sm + W_FNH, 0,
                    0, 0, 0, 0, 0, mt4, 0, o2, 0, sG + 72, 0.f);
            else
                mma_tile<2, 5, 2, 0, true>(sm + W_A2H, sm + W_A2L, sm + W_FNH, 0,
                    0, 0, 0, 0, 0, mt4, 32, o2, 0, sG + 72, 0.f);
        }
        if (h + 1 < H) { DO_P2(); }   // reads T(h+1), writes S(h+1)
#pragma unroll
        for (int off = 16; off; off >>= 1) ss += __shfl_xor_sync(0xffffffffu, ss, off);
        if ((tid & 31) == 0) swarp[h * 16 + w] = ss;
        cp_wait0();
        __syncthreads();
    }

    if (tid < H) {
        float t = 0.f;
#pragma unroll
        for (int ww = 0; ww < 16; ww++) t += swarp[tid * 16 + ww];
        g_norms[b * H + tid] = sqrtf(t);
    }
    __threadfence();
    __syncthreads();
    if (tid == 0) *sflag = ((atomicAdd(&g_ctr, 1) % BSZ) == BSZ - 1) ? 1 : 0;
    __syncthreads();
    if (*sflag) {
        float s = 0.f;
        for (int i = tid; i < BSZ * H; i += NT) s += g_norms[i];
#pragma unroll
        for (int off = 16; off; off >>= 1) s += __shfl_xor_sync(0xffffffffu, s, off);
        if ((tid & 31) == 0) swarp[w] = s;
        __syncthreads();
        if (tid == 0) {
            float t = 0.f;
#pragma unroll
            for (int ww = 0; ww < 16; ww++) t += swarp[ww];
            *out_loss = t / (float)(BSZ * H);
        }
    }
}

extern "C" void kernel_launch(void* const* d_in, const int* in_sizes, int n_in,
                              void* d_out, int out_size)
{
    const float* Fn  = (const float*)d_in[0];
    const float* Fr  = (const float*)d_in[1];
    const float* Wq1 = (const float*)d_in[2];
    const float* bq1 = (const float*)d_in[3];
    const float* Wk1 = (const float*)d_in[4];
    const float* bk1 = (const float*)d_in[5];
    const float* Wq2 = (const float*)d_in[6];
    const float* bq2 = (const float*)d_in[7];
    const float* Wk2 = (const float*)d_in[8];
    const float* bk2 = (const float*)d_in[9];
    const float* Wg  = (const float*)d_in[10];
    const float* bg  = (const float*)d_in[11];
    float* out = (float*)d_out;

    prep_kernel<<<BSZ + 20, 256>>>(Fn, Fr, Wg, bg, Wq1, bq1, Wk1, bk1, Wq2, bq2, Wk2, bk2);
    const int smem_bytes = SMEM_WORDS * 4;
    cudaFuncSetAttribute(fused_kernel, cudaFuncAttributeMaxDynamicSharedMemorySize, smem_bytes);
    fused_kernel<<<BSZ, NT, smem_bytes>>>(Fn, Fr, out, out + (size_t)out_size - 1);
}